// round 12
// baseline (speedup 1.0000x reference)
#include <cuda_runtime.h>
#include <cuda_bf16.h>
#include <math.h>
#include <stdint.h>

// ---------------- problem constants ----------------
#define Bb   2
#define SS   2048
#define DD   1024
#define HH   16
#define HDIM 64
#define EE   4
#define KSEL 2
#define HIDD 4096
#define TT   (Bb*SS)   // 4096 tokens

// ---------------- fp32 scratch ----------------
static const size_t OFF_QKV   = 0;                                   // TT*3*DD
static const size_t OFF_X1    = OFF_QKV   + (size_t)TT*3*DD;         // TT*DD
static const size_t OFF_H2F   = OFF_X1    + (size_t)TT*DD;           // TT*DD
static const size_t OFF_SDOWN = OFF_H2F   + (size_t)TT*DD;           // TT*DD
static const size_t OFF_EO    = OFF_SDOWN + (size_t)TT*DD;           // EE*TT*DD
static const size_t OFF_PROBS = OFF_EO    + (size_t)EE*TT*DD;        // TT*EE
static const size_t OFF_TOPW  = OFF_PROBS + (size_t)TT*EE;           // TT*KSEL
static const size_t F_TOTAL   = OFF_TOPW  + (size_t)TT*KSEL;
__device__ float g_f[F_TOTAL];

// ---------------- bf16 hi/lo planes ----------------
static const size_t BO_WQKV = 0;                                 // 3*DD*DD
static const size_t BO_WO   = BO_WQKV + (size_t)3*DD*DD;         // DD*DD
static const size_t BO_WEUP = BO_WO   + (size_t)DD*DD;           // EE*HIDD*DD
static const size_t BO_WEDN = BO_WEUP + (size_t)EE*HIDD*DD;      // EE*DD*HIDD
static const size_t BO_WSUP = BO_WEDN + (size_t)EE*DD*HIDD;      // HIDD*DD
static const size_t BO_WSDN = BO_WSUP + (size_t)HIDD*DD;         // DD*HIDD
static const size_t BO_H    = BO_WSDN + (size_t)DD*HIDD;         // TT*DD
static const size_t BO_ATTN = BO_H    + (size_t)TT*DD;           // TT*DD
static const size_t BO_H2   = BO_ATTN + (size_t)TT*DD;           // TT*DD
static const size_t BO_SUP  = BO_H2   + (size_t)TT*DD;           // TT*HIDD
static const size_t BO_UPB  = BO_SUP  + (size_t)TT*HIDD;         // EE*TT*HIDD
static const size_t B_TOTAL = BO_UPB  + (size_t)EE*TT*HIDD;
__device__ __nv_bfloat16 g_bh[B_TOTAL];
__device__ __nv_bfloat16 g_bl[B_TOTAL];

// ---------------- int scratch ----------------
static const size_t IOFF_SLOT    = 0;                       // EE*TT
static const size_t IOFF_TOKSLOT = IOFF_SLOT + EE*TT;       // TT*KSEL
static const size_t IOFF_TOPI    = IOFF_TOKSLOT + TT*KSEL;  // TT*KSEL
static const size_t IOFF_CNT     = IOFF_TOPI + TT*KSEL;     // EE
__device__ int g_i[IOFF_CNT + EE];

// ---------------- helpers ----------------
__device__ __forceinline__ float gelu_tanh(float x) {
    float z = 0.7978845608028654f * (x + 0.044715f * x * x * x);
    float e = __expf(2.f * z);
    float th = 1.f - 2.f / (e + 1.f);
    return 0.5f * x * (1.f + th);
}

__device__ __forceinline__ void mma_bf16(float* d, const uint32_t* a, const uint32_t* b) {
    asm volatile(
        "mma.sync.aligned.m16n8k16.row.col.f32.bf16.bf16.f32 "
        "{%0,%1,%2,%3}, {%4,%5,%6,%7}, {%8,%9}, {%0,%1,%2,%3};\n"
        : "+f"(d[0]), "+f"(d[1]), "+f"(d[2]), "+f"(d[3])
        : "r"(a[0]), "r"(a[1]), "r"(a[2]), "r"(a[3]), "r"(b[0]), "r"(b[1]));
}

__device__ __forceinline__ void ldsm4(uint32_t* r, uint32_t addr) {
    asm volatile("ldmatrix.sync.aligned.m8n8.x4.shared.b16 {%0,%1,%2,%3}, [%4];"
                 : "=r"(r[0]), "=r"(r[1]), "=r"(r[2]), "=r"(r[3]) : "r"(addr));
}

__device__ __forceinline__ void split2(float x, float y, uint32_t& hi, uint32_t& lo) {
    __nv_bfloat16 hx = __float2bfloat16_rn(x);
    __nv_bfloat16 hy = __float2bfloat16_rn(y);
    __nv_bfloat16 lx = __float2bfloat16_rn(x - __bfloat162float(hx));
    __nv_bfloat16 ly = __float2bfloat16_rn(y - __bfloat162float(hy));
    __nv_bfloat162 h2 = __nv_bfloat162(hx, hy);
    __nv_bfloat162 l2 = __nv_bfloat162(lx, ly);
    hi = *reinterpret_cast<uint32_t*>(&h2);
    lo = *reinterpret_cast<uint32_t*>(&l2);
}

__device__ __forceinline__ void cpa16(uint32_t dst, const void* src, int srcbytes) {
    asm volatile("cp.async.cg.shared.global [%0], [%1], 16, %2;"
                 :: "r"(dst), "l"(src), "r"(srcbytes));
}
__device__ __forceinline__ void cpa_commit() { asm volatile("cp.async.commit_group;"); }
__device__ __forceinline__ void cpa_wait_all() { asm volatile("cp.async.wait_group 0;"); }

// ---------------- fp32 -> bf16 hi/lo convert ----------------
__global__ void conv_kernel(const float* __restrict__ in, __nv_bfloat16* __restrict__ hi,
                            __nv_bfloat16* __restrict__ lo, int n) {
    int i = (blockIdx.x * blockDim.x + threadIdx.x) * 4;
    if (i >= n) return;
    float4 v = *(const float4*)(in + i);
    uint32_t h0, l0, h1, l1;
    split2(v.x, v.y, h0, l0);
    split2(v.z, v.w, h1, l1);
    *(uint32_t*)(hi + i)     = h0;
    *(uint32_t*)(hi + i + 2) = h1;
    *(uint32_t*)(lo + i)     = l0;
    *(uint32_t*)(lo + i + 2) = l1;
}

// ---------------- LayerNorm ----------------
template <int MODE>
__global__ void ln_kernel(const float* __restrict__ x, const float* __restrict__ g,
                          const float* __restrict__ b, float* __restrict__ outf,
                          __nv_bfloat16* __restrict__ ohi, __nv_bfloat16* __restrict__ olo) {
    int t = blockIdx.x, tid = threadIdx.x;
    const float* xr = x + (size_t)t * DD;
    float v[4], s = 0.f, sq = 0.f;
#pragma unroll
    for (int k = 0; k < 4; k++) {
        v[k] = xr[tid + k * 256];
        s += v[k]; sq += v[k] * v[k];
    }
    __shared__ float rs[256], rq[256];
    rs[tid] = s; rq[tid] = sq;
    __syncthreads();
    for (int o = 128; o > 0; o >>= 1) {
        if (tid < o) { rs[tid] += rs[tid + o]; rq[tid] += rq[tid + o]; }
        __syncthreads();
    }
    float mean = rs[0] * (1.f / DD);
    float var  = rq[0] * (1.f / DD) - mean * mean;
    float inv  = rsqrtf(var + 1e-5f);
#pragma unroll
    for (int k = 0; k < 4; k++) {
        int d = tid + k * 256;
        float val = (v[k] - mean) * inv * g[d] + b[d];
        if (MODE == 1) outf[(size_t)t * DD + d] = val;
        __nv_bfloat16 hx = __float2bfloat16_rn(val);
        __nv_bfloat16 lx = __float2bfloat16_rn(val - __bfloat162float(hx));
        ohi[(size_t)t * DD + d] = hx;
        olo[(size_t)t * DD + d] = lx;
    }
}

// ---------------- tensor-core NT GEMM, split-bf16 planes ----------------------
// C[M,N] = A[M,K]*Bw[N,K]^T + bias. Block 128x128, 4 warps of 64x64,
// k-tile 32, 2-stage cp.async. EPI: 0 fp32; 1 gelu->bf16 planes; 2 fp32+resid
#define LDAH 40            // smem row pitch in halves
#define ARR_B   10240      // one plane: 128 rows * 80B
#define STAGE_B 40960      // 4 planes
#define SMEM_GEMM 81920    // 2 stages
template <int EPI>
__global__ void __launch_bounds__(128) hgemm_nt(
    const __nv_bfloat16* __restrict__ Ahi, const __nv_bfloat16* __restrict__ Alo,
    const __nv_bfloat16* __restrict__ Bhi, const __nv_bfloat16* __restrict__ Blo,
    const float* __restrict__ bias, const float* __restrict__ resid,
    float* __restrict__ Cf, __nv_bfloat16* __restrict__ Chi, __nv_bfloat16* __restrict__ Clo,
    int M, int N, int Kd,
    const int* __restrict__ rowIdx, const int* __restrict__ cnt,
    size_t aZ, size_t bZ, size_t biasZ, size_t cZ, size_t idxZ) {
    int z = blockIdx.z;
    Ahi += (size_t)z * aZ; Alo += (size_t)z * aZ;
    Bhi += (size_t)z * bZ; Blo += (size_t)z * bZ;
    bias += (size_t)z * biasZ;
    if (EPI == 1) { Chi += (size_t)z * cZ; Clo += (size_t)z * cZ; }
    else          { Cf  += (size_t)z * cZ; }
    if (rowIdx) rowIdx += (size_t)z * idxZ;
    if (cnt) M = cnt[z];
    int mBase = blockIdx.y * 128;
    if (mBase >= M) return;
    int n0 = blockIdx.x * 128;

    extern __shared__ __align__(16) uint16_t smem_dyn[];
    uint32_t smemBase = (uint32_t)__cvta_generic_to_shared(smem_dyn);

    int tid = threadIdx.x;
    int wid = tid >> 5, lane = tid & 31;
    int warp_m = (wid & 1) * 64;
    int warp_n = (wid >> 1) * 64;

    // ---- cp.async mapping: seg i -> row (tid>>2)+32*i, 16B chunk (tid&3) ----
    ptrdiff_t dAlo = Alo - Ahi;
    ptrdiff_t dBlo = Blo - Bhi;
    int rowB0 = tid >> 2;
    int kh0   = (tid & 3) * 8;   // halves offset within k-tile
    const __nv_bfloat16* aHiP[4];
    int aOK[4];
    uint32_t sOff[4];
#pragma unroll
    for (int i = 0; i < 4; i++) {
        int row = rowB0 + 32 * i;
        sOff[i] = (uint32_t)(row * LDAH + kh0) * 2;
        int gmr = mBase + row;
        bool ok = gmr < M;
        int sr = ok ? (rowIdx ? rowIdx[gmr] : gmr) : 0;
        aHiP[i] = Ahi + (size_t)sr * Kd + kh0;
        aOK[i] = ok ? 16 : 0;
    }
    const __nv_bfloat16* bHi0 = Bhi + (size_t)(n0 + rowB0) * Kd + kh0;

    // ---- ldmatrix offsets ----
    uint32_t aOff[4];
#pragma unroll
    for (int mt = 0; mt < 4; mt++) {
        int row = warp_m + mt * 16 + (lane & 15);
        int colh = (lane >> 4) * 8;
        aOff[mt] = (uint32_t)(row * LDAH + colh) * 2;
    }
    uint32_t bOff[4];
#pragma unroll
    for (int np = 0; np < 4; np++) {
        int row = warp_n + np * 16 + (lane & 7) + ((lane >> 4) << 3);
        int colh = ((lane >> 3) & 1) * 8;
        bOff[np] = (uint32_t)(row * LDAH + colh) * 2;
    }

    float c[4][8][4];
#pragma unroll
    for (int i = 0; i < 4; i++)
#pragma unroll
        for (int j = 0; j < 8; j++)
#pragma unroll
            for (int k = 0; k < 4; k++) c[i][j][k] = 0.f;

    int nK = Kd >> 5;

    // prefetch stage 0
    {
        uint32_t sb = smemBase;
#pragma unroll
        for (int i = 0; i < 4; i++) {
            const __nv_bfloat16* bp = bHi0 + (size_t)(32 * i) * Kd;
            cpa16(sb + sOff[i],             aHiP[i], aOK[i]);
            cpa16(sb + ARR_B + sOff[i],     aHiP[i] + dAlo, aOK[i]);
            cpa16(sb + 2 * ARR_B + sOff[i], bp, 16);
            cpa16(sb + 3 * ARR_B + sOff[i], bp + dBlo, 16);
        }
        cpa_commit();
    }

    for (int kt = 0; kt < nK; kt++) {
        int cur = kt & 1;
        cpa_wait_all();
        __syncthreads();
        if (kt + 1 < nK) {
            uint32_t sb = smemBase + (cur ^ 1) * STAGE_B;
            int koff = (kt + 1) * 32;
#pragma unroll
            for (int i = 0; i < 4; i++) {
                const __nv_bfloat16* bp = bHi0 + (size_t)(32 * i) * Kd + koff;
                cpa16(sb + sOff[i],             aHiP[i] + koff, aOK[i]);
                cpa16(sb + ARR_B + sOff[i],     aHiP[i] + dAlo + koff, aOK[i]);
                cpa16(sb + 2 * ARR_B + sOff[i], bp, 16);
                cpa16(sb + 3 * ARR_B + sOff[i], bp + dBlo, 16);
            }
            cpa_commit();
        }
        uint32_t stageB = smemBase + cur * STAGE_B;
#pragma unroll
        for (int ks = 0; ks < 2; ks++) {
            uint32_t kb = ks * 32;
            uint32_t ah[4][4], al[4][4], bh[8][2], bl[8][2];
#pragma unroll
            for (int mt = 0; mt < 4; mt++) {
                ldsm4(ah[mt], stageB + aOff[mt] + kb);
                ldsm4(al[mt], stageB + ARR_B + aOff[mt] + kb);
            }
#pragma unroll
            for (int np = 0; np < 4; np++) {
                uint32_t r[4];
                ldsm4(r, stageB + 2 * ARR_B + bOff[np] + kb);
                bh[2 * np][0] = r[0]; bh[2 * np][1] = r[1];
                bh[2 * np + 1][0] = r[2]; bh[2 * np + 1][1] = r[3];
                ldsm4(r, stageB + 3 * ARR_B + bOff[np] + kb);
                bl[2 * np][0] = r[0]; bl[2 * np][1] = r[1];
                bl[2 * np + 1][0] = r[2]; bl[2 * np + 1][1] = r[3];
            }
#pragma unroll
            for (int mt = 0; mt < 4; mt++)
#pragma unroll
                for (int nt = 0; nt < 8; nt++) {
                    mma_bf16(c[mt][nt], ah[mt], bh[nt]);
                    mma_bf16(c[mt][nt], ah[mt], bl[nt]);
                    mma_bf16(c[mt][nt], al[mt], bh[nt]);
                }
        }
    }

    // ---- epilogue ----
#pragma unroll
    for (int mt = 0; mt < 4; mt++) {
#pragma unroll
        for (int nt = 0; nt < 8; nt++) {
            int col = n0 + warp_n + nt * 8 + (lane & 3) * 2;
            float2 bb = *(const float2*)(bias + col);
#pragma unroll
            for (int half = 0; half < 2; half++) {
                int r = mBase + warp_m + mt * 16 + (lane >> 2) + half * 8;
                if (r >= M) continue;
                float v0 = c[mt][nt][half * 2 + 0] + bb.x;
                float v1 = c[mt][nt][half * 2 + 1] + bb.y;
                if (EPI == 1) {
                    v0 = gelu_tanh(v0); v1 = gelu_tanh(v1);
                    uint32_t hi, lo;
                    split2(v0, v1, hi, lo);
                    *(uint32_t*)(Chi + (size_t)r * N + col) = hi;
                    *(uint32_t*)(Clo + (size_t)r * N + col) = lo;
                } else {
                    if (EPI == 2) {
                        float2 rr = *(const float2*)(resid + (size_t)r * N + col);
                        v0 += rr.x; v1 += rr.y;
                    }
                    *(float2*)(Cf + (size_t)r * N + col) = make_float2(v0, v1);
                }
            }
        }
    }
}

// ---------------- causal flash attention (bf16 hi/lo output) ------------------
__global__ void __launch_bounds__(512) attn_kernel(const float* __restrict__ qkv,
                                                   __nv_bfloat16* __restrict__ ohi,
                                                   __nv_bfloat16* __restrict__ olo) {
    __shared__ float q_s[16][64];
    __shared__ float k_s[32][65];
    __shared__ float v_s[32][64];
    int bh = blockIdx.y;
    int b = bh >> 4, h = bh & 15;
    int q0 = blockIdx.x * 16;
    int tid = threadIdx.x;
    int w = tid >> 5, lane = tid & 31;

    {
        int i = tid * 2;
        int qi = i >> 6, d = i & 63;
        const float* src = qkv + ((size_t)(b * SS + q0 + qi)) * (3 * DD) + h * 64 + d;
        float2 v = *(const float2*)src;
        q_s[qi][d]     = v.x * 0.125f;
        q_s[qi][d + 1] = v.y * 0.125f;
    }
    __syncthreads();
    float qr[64];
#pragma unroll
    for (int d = 0; d < 64; d++) qr[d] = q_s[w][d];

    int q = q0 + w;
    float M = -1e30f, L = 0.f, o0 = 0.f, o1 = 0.f;
    int nkeys = q0 + 16;

    for (int t0 = 0; t0 < nkeys; t0 += 32) {
        __syncthreads();
        {
            int r  = tid >> 4;
            int c4 = (tid & 15) * 4;
            int key = t0 + r;
            float4 kv = make_float4(0, 0, 0, 0), vv = make_float4(0, 0, 0, 0);
            if (key < SS) {
                size_t base = ((size_t)(b * SS + key)) * (3 * DD) + h * 64 + c4;
                kv = *(const float4*)(qkv + DD + base);
                vv = *(const float4*)(qkv + 2 * DD + base);
            }
            k_s[r][c4 + 0] = kv.x; k_s[r][c4 + 1] = kv.y;
            k_s[r][c4 + 2] = kv.z; k_s[r][c4 + 3] = kv.w;
            *(float4*)&v_s[r][c4] = vv;
        }
        __syncthreads();

        int key = t0 + lane;
        bool act = (key <= q);
        float s = -1e30f;
        if (act) {
            float a = 0.f;
#pragma unroll
            for (int d = 0; d < 64; d++) a += qr[d] * k_s[lane][d];
            s = a;
        }
        float mcur = s;
#pragma unroll
        for (int off = 16; off > 0; off >>= 1)
            mcur = fmaxf(mcur, __shfl_xor_sync(0xffffffffu, mcur, off));
        if (mcur > M) {
            float sc = __expf(M - mcur);
            o0 *= sc; o1 *= sc; L *= sc;
            M = mcur;
        }
        float p = act ? __expf(s - M) : 0.f;
        float ls = p;
#pragma unroll
        for (int off = 16; off > 0; off >>= 1)
            ls += __shfl_xor_sync(0xffffffffu, ls, off);
        L += ls;
#pragma unroll
        for (int j = 0; j < 32; j++) {
            float pj = __shfl_sync(0xffffffffu, p, j);
            float2 vv = *(const float2*)&v_s[j][lane * 2];
            o0 += pj * vv.x;
            o1 += pj * vv.y;
        }
    }
    float inv = 1.f / L;
    uint32_t hi, lo;
    split2(o0 * inv, o1 * inv, hi, lo);
    size_t off = ((size_t)(b * SS + q)) * DD + h * 64 + lane * 2;
    *(uint32_t*)(ohi + off) = hi;
    *(uint32_t*)(olo + off) = lo;
}

// ---------------- MoE router ----------------
__global__ void router_kernel(const float* __restrict__ h2, const float* __restrict__ Wg,
                              float* __restrict__ probs, float* __restrict__ topw,
                              int* __restrict__ topi, int* __restrict__ slot_tok,
                              int* __restrict__ tok_slot, int* __restrict__ cnt) {
    int t = blockIdx.x, tid = threadIdx.x;  // 128 threads
    const float* hr = h2 + (size_t)t * DD;
    float a0 = 0, a1 = 0, a2 = 0, a3 = 0;
    for (int d = tid; d < DD; d += 128) {
        float hv = hr[d];
        a0 += hv * Wg[d];
        a1 += hv * Wg[DD + d];
        a2 += hv * Wg[2 * DD + d];
        a3 += hv * Wg[3 * DD + d];
    }
    __shared__ float r[4][128];
    r[0][tid] = a0; r[1][tid] = a1; r[2][tid] = a2; r[3][tid] = a3;
    __syncthreads();
    for (int o = 64; o > 0; o >>= 1) {
        if (tid < o) {
#pragma unroll
            for (int e = 0; e < 4; e++) r[e][tid] += r[e][tid + o];
        }
        __syncthreads();
    }
    if (tid == 0) {
        float l[4] = {r[0][0], r[1][0], r[2][0], r[3][0]};
        float m = fmaxf(fmaxf(l[0], l[1]), fmaxf(l[2], l[3]));
        float p[4], sum = 0.f;
#pragma unroll
        for (int e = 0; e < 4; e++) { p[e] = __expf(l[e] - m); sum += p[e]; }
#pragma unroll
        for (int e = 0; e < 4; e++) { p[e] /= sum; probs[t * 4 + e] = p[e]; }
        int i0 = 0;
#pragma unroll
        for (int e = 1; e < 4; e++) if (p[e] > p[i0]) i0 = e;
        int i1 = -1;
#pragma unroll
        for (int e = 0; e < 4; e++)
            if (e != i0 && (i1 < 0 || p[e] > p[i1])) i1 = e;
        float w0 = p[i0], w1 = p[i1], ws = w0 + w1;
        w0 /= ws; w1 /= ws;
        int pos0 = atomicAdd(&cnt[i0], 1);
        slot_tok[i0 * TT + pos0] = t;
        tok_slot[t * 2]     = i0 * TT + pos0;
        int pos1 = atomicAdd(&cnt[i1], 1);
        slot_tok[i1 * TT + pos1] = t;
        tok_slot[t * 2 + 1] = i1 * TT + pos1;
        topw[t * 2] = w0; topw[t * 2 + 1] = w1;
        topi[t * 2] = i0; topi[t * 2 + 1] = i1;
    }
}

// ---------------- aux loss ----------------
__global__ void aux_kernel(const float* __restrict__ probs, const int* __restrict__ topi,
                           float* __restrict__ auxout) {
    int tid = threadIdx.x;  // 512
    float ps[4] = {0, 0, 0, 0};
    float cs[4] = {0, 0, 0, 0};
    for (int t = tid; t < TT; t += 512) {
#pragma unroll
        for (int e = 0; e < 4; e++) ps[e] += probs[t * 4 + e];
        cs[topi[t * 2]] += 1.f;
        cs[topi[t * 2 + 1]] += 1.f;
    }
    __shared__ float sp[4][512], sc[4][512];
#pragma unroll
    for (int e = 0; e < 4; e++) { sp[e][tid] = ps[e]; sc[e][tid] = cs[e]; }
    __syncthreads();
    for (int o = 256; o > 0; o >>= 1) {
        if (tid < o) {
#pragma unroll
            for (int e = 0; e < 4; e++) {
                sp[e][tid] += sp[e][tid + o];
                sc[e][tid] += sc[e][tid + o];
            }
        }
        __syncthreads();
    }
    if (tid == 0) {
        float aux = 0.f;
#pragma unroll
        for (int e = 0; e < 4; e++) {
            float fi = sc[e][0] / (float)(TT * KSEL);
            float Pi = sp[e][0] / (float)TT;
            aux += fi * Pi;
        }
        auxout[0] = 0.01f * (float)EE * aux;
    }
}

// ---------------- final combine (scalar stores) ----------------
__global__ void combine_kernel(const float* __restrict__ x1, const float* __restrict__ sdown,
                               const float* __restrict__ eo, const float* __restrict__ topw,
                               const int* __restrict__ tok_slot, float* __restrict__ xout) {
    int t = blockIdx.x, tid = threadIdx.x;
    int c = tid * 4;
    int s0 = tok_slot[t * 2], s1 = tok_slot[t * 2 + 1];
    float w0 = topw[t * 2], w1 = topw[t * 2 + 1];
    float4 a  = *(const float4*)(x1 + (size_t)t * DD + c);
    float4 sd = *(const float4*)(sdown + (size_t)t * DD + c);
    float4 e0 = *(const float4*)(eo + (size_t)s0 * DD + c);
    float4 e1 = *(const float4*)(eo + (size_t)s1 * DD + c);
    float* o = xout + (size_t)t * DD + c;
    o[0] = a.x + sd.x + w0 * e0.x + w1 * e1.x;
    o[1] = a.y + sd.y + w0 * e0.y + w1 * e1.y;
    o[2] = a.z + sd.z + w0 * e0.z + w1 * e1.z;
    o[3] = a.w + sd.w + w0 * e0.w + w1 * e1.w;
}

// ---------------- launch ------------------------------------------------------
extern "C" void kernel_launch(void* const* d_in, const int* in_sizes, int n_in,
                              void* d_out, int out_size) {
    const float* x      = (const float*)d_in[0];
    const float* ln1_g  = (const float*)d_in[1];
    const float* ln1_b  = (const float*)d_in[2];
    const float* Wqkv   = (const float*)d_in[3];
    const float* bqkv   = (const float*)d_in[4];
    const float* Wo     = (const float*)d_in[5];
    const float* bo     = (const float*)d_in[6];
    const float* ln2_g  = (const float*)d_in[7];
    const float* ln2_b  = (const float*)d_in[8];
    const float* Wg     = (const float*)d_in[9];
    const float* We_up  = (const float*)d_in[10];
    const float* be_up  = (const float*)d_in[11];
    const float* We_dn  = (const float*)d_in[12];
    const float* be_dn  = (const float*)d_in[13];
    const float* Ws_up  = (const float*)d_in[14];
    const float* bs_up  = (const float*)d_in[15];
    const float* Ws_dn  = (const float*)d_in[16];
    const float* bs_dn  = (const float*)d_in[17];

    float* F = nullptr; int* I = nullptr;
    __nv_bfloat16* BH = nullptr; __nv_bfloat16* BL = nullptr;
    cudaGetSymbolAddress((void**)&F, g_f);
    cudaGetSymbolAddress((void**)&I, g_i);
    cudaGetSymbolAddress((void**)&BH, g_bh);
    cudaGetSymbolAddress((void**)&BL, g_bl);

    // one-time setup: func attrs + side streams/events (host objects; no device allocs)
    static bool init_done = false;
    static cudaStream_t sA, sB;
    static cudaEvent_t evStart, evWo, evConvs, evRouter, evShared;
    if (!init_done) {
        cudaFuncSetAttribute(hgemm_nt<0>, cudaFuncAttributeMaxDynamicSharedMemorySize, SMEM_GEMM);
        cudaFuncSetAttribute(hgemm_nt<1>, cudaFuncAttributeMaxDynamicSharedMemorySize, SMEM_GEMM);
        cudaFuncSetAttribute(hgemm_nt<2>, cudaFuncAttributeMaxDynamicSharedMemorySize, SMEM_GEMM);
        cudaStreamCreateWithFlags(&sA, cudaStreamNonBlocking);
        cudaStreamCreateWithFlags(&sB, cudaStreamNonBlocking);
        cudaEventCreateWithFlags(&evStart,  cudaEventDisableTiming);
        cudaEventCreateWithFlags(&evWo,     cudaEventDisableTiming);
        cudaEventCreateWithFlags(&evConvs,  cudaEventDisableTiming);
        cudaEventCreateWithFlags(&evRouter, cudaEventDisableTiming);
        cudaEventCreateWithFlags(&evShared, cudaEventDisableTiming);
        init_done = true;
    }

    float* qkv   = F + OFF_QKV;
    float* x1    = F + OFF_X1;
    float* h2f   = F + OFF_H2F;
    float* sdown = F + OFF_SDOWN;
    float* eob   = F + OFF_EO;
    float* probs = F + OFF_PROBS;
    float* topw  = F + OFF_TOPW;
    int* slot_tok = I + IOFF_SLOT;
    int* tok_slot = I + IOFF_TOKSLOT;
    int* topi     = I + IOFF_TOPI;
    int* cnt      = I + IOFF_CNT;

    float* outp = (float*)d_out;
    float* auxp = nullptr;
    float* xout = outp;
    if (out_size == TT * DD + 1) { auxp = outp; xout = outp + 1; }

    cudaMemsetAsync(cnt, 0, EE * sizeof(int));

    // fork stream B for weight conversions not needed immediately
    cudaEventRecord(evStart, 0);
    cudaStreamWaitEvent(sB, evStart, 0);
    conv_kernel<<<(DD * DD) / 1024, 256, 0, sB>>>(Wo, BH + BO_WO, BL + BO_WO, DD * DD);
    cudaEventRecord(evWo, sB);
    conv_kernel<<<(EE * HIDD * DD) / 1024, 256, 0, sB>>>(We_up, BH + BO_WEUP, BL + BO_WEUP, EE * HIDD * DD);
    conv_kernel<<<(EE * DD * HIDD) / 1024, 256, 0, sB>>>(We_dn, BH + BO_WEDN, BL + BO_WEDN, EE * DD * HIDD);
    conv_kernel<<<(HIDD * DD) / 1024, 256, 0, sB>>>(Ws_up, BH + BO_WSUP, BL + BO_WSUP, HIDD * DD);
    conv_kernel<<<(DD * HIDD) / 1024, 256, 0, sB>>>(Ws_dn, BH + BO_WSDN, BL + BO_WSDN, DD * HIDD);
    cudaEventRecord(evConvs, sB);

    // main chain
    conv_kernel<<<(3 * DD * DD) / 1024, 256>>>(Wqkv, BH + BO_WQKV, BL + BO_WQKV, 3 * DD * DD);
    // 1) LN1 -> bf16 planes
    ln_kernel<0><<<TT, 256>>>(x, ln1_g, ln1_b, nullptr, BH + BO_H, BL + BO_H);
    // 2) QKV projection
    hgemm_nt<0><<<dim3(24, 32, 1), 128, SMEM_GEMM>>>(
        BH + BO_H, BL + BO_H, BH + BO_WQKV, BL + BO_WQKV, bqkv, nullptr,
        qkv, nullptr, nullptr, TT, 3 * DD, DD, nullptr, nullptr, 0, 0, 0, 0, 0);
    // 3) causal attention -> bf16 planes (overlaps stream-B convs)
    attn_kernel<<<dim3(SS / 16, Bb * HH), 512>>>(qkv, BH + BO_ATTN, BL + BO_ATTN);
    // 4) output proj + residual -> x1 fp32 (needs Wo planes from stream B)
    cudaStreamWaitEvent(0, evWo, 0);
    hgemm_nt<2><<<dim3(8, 32, 1), 128, SMEM_GEMM>>>(
        BH + BO_ATTN, BL + BO_ATTN, BH + BO_WO, BL + BO_WO, bo, x,
        x1, nullptr, nullptr, TT, DD, DD, nullptr, nullptr, 0, 0, 0, 0, 0);
    // 5) LN2 -> fp32 + bf16 planes
    ln_kernel<1><<<TT, 256>>>(x1, ln2_g, ln2_b, h2f, BH + BO_H2, BL + BO_H2);
    // 6) router
    router_kernel<<<TT, 128>>>(h2f, Wg, probs, topw, topi, slot_tok, tok_slot, cnt);
    // 7) aux loss
    if (auxp) aux_kernel<<<1, 512>>>(probs, topi, auxp);

    // fork: shared-expert chain on stream A, expert chain on main
    cudaEventRecord(evRouter, 0);
    cudaStreamWaitEvent(sA, evRouter, 0);
    cudaStreamWaitEvent(sA, evConvs, 0);
    // 10) shared expert up (gelu -> bf16 planes)  [stream A]
    hgemm_nt<1><<<dim3(32, 32, 1), 128, SMEM_GEMM, sA>>>(
        BH + BO_H2, BL + BO_H2, BH + BO_WSUP, BL + BO_WSUP, bs_up, nullptr,
        nullptr, BH + BO_SUP, BL + BO_SUP, TT, HIDD, DD, nullptr, nullptr, 0, 0, 0, 0, 0);
    // 11) shared expert down -> sdown fp32       [stream A]
    hgemm_nt<0><<<dim3(8, 32, 1), 128, SMEM_GEMM, sA>>>(
        BH + BO_SUP, BL + BO_SUP, BH + BO_WSDN, BL + BO_WSDN, bs_dn, nullptr,
        sdown, nullptr, nullptr, TT, DD, HIDD, nullptr, nullptr, 0, 0, 0, 0, 0);
    cudaEventRecord(evShared, sA);

    // 8) expert up (gathered, gelu -> bf16 planes) [main; needs stream-B convs]
    cudaStreamWaitEvent(0, evConvs, 0);
    hgemm_nt<1><<<dim3(32, 32, 4), 128, SMEM_GEMM>>>(
        BH + BO_H2, BL + BO_H2, BH + BO_WEUP, BL + BO_WEUP, be_up, nullptr,
        nullptr, BH + BO_UPB, BL + BO_UPB, TT, HIDD, DD, slot_tok, cnt,
        0, (size_t)HIDD * DD, (size_t)HIDD, (size_t)TT * HIDD, (size_t)TT);
    // 9) expert down -> eob fp32                   [main]
    hgemm_nt<0><<<dim3(8, 32, 4), 128, SMEM_GEMM>>>(
        BH + BO_UPB, BL + BO_UPB, BH + BO_WEDN, BL + BO_WEDN, be_dn, nullptr,
        eob, nullptr, nullptr, TT, DD, HIDD, nullptr, cnt,
        (size_t)TT * HIDD, (size_t)DD * HIDD, (size_t)DD, (size_t)TT * DD, 0);

    // join: combine needs both chains
    cudaStreamWaitEvent(0, evShared, 0);
    // 12) combine
    combine_kernel<<<TT, 256>>>(x1, sdown, eob, topw, tok_slot, xout);
}

// round 14
// speedup vs baseline: 1.8799x; 1.8799x over previous
#include <cuda_runtime.h>
#include <cuda_bf16.h>
#include <math.h>
#include <stdint.h>

// ---------------- problem constants ----------------
#define Bb   2
#define SS   2048
#define DD   1024
#define HH   16
#define HDIM 64
#define EE   4
#define KSEL 2
#define HIDD 4096
#define TT   (Bb*SS)   // 4096 tokens

// ---------------- fp32 scratch ----------------
static const size_t OFF_QKV   = 0;                                   // TT*3*DD
static const size_t OFF_X1    = OFF_QKV   + (size_t)TT*3*DD;         // TT*DD
static const size_t OFF_H2F   = OFF_X1    + (size_t)TT*DD;           // TT*DD
static const size_t OFF_SDOWN = OFF_H2F   + (size_t)TT*DD;           // TT*DD
static const size_t OFF_EO    = OFF_SDOWN + (size_t)TT*DD;           // EE*TT*DD
static const size_t OFF_PROBS = OFF_EO    + (size_t)EE*TT*DD;        // TT*EE
static const size_t OFF_TOPW  = OFF_PROBS + (size_t)TT*EE;           // TT*KSEL
static const size_t F_TOTAL   = OFF_TOPW  + (size_t)TT*KSEL;
__device__ float g_f[F_TOTAL];

// ---------------- bf16 hi/lo planes (weights contiguous & in conv order) ------
static const size_t BO_WQKV = 0;                                 // 3*DD*DD
static const size_t BO_WO   = BO_WQKV + (size_t)3*DD*DD;         // DD*DD
static const size_t BO_WEUP = BO_WO   + (size_t)DD*DD;           // EE*HIDD*DD
static const size_t BO_WEDN = BO_WEUP + (size_t)EE*HIDD*DD;      // EE*DD*HIDD
static const size_t BO_WSUP = BO_WEDN + (size_t)EE*DD*HIDD;      // HIDD*DD
static const size_t BO_WSDN = BO_WSUP + (size_t)HIDD*DD;         // DD*HIDD
static const size_t BO_H    = BO_WSDN + (size_t)DD*HIDD;         // TT*DD
static const size_t BO_ATTN = BO_H    + (size_t)TT*DD;           // TT*DD
static const size_t BO_H2   = BO_ATTN + (size_t)TT*DD;           // TT*DD
static const size_t BO_SUP  = BO_H2   + (size_t)TT*DD;           // TT*HIDD
static const size_t BO_UPB  = BO_SUP  + (size_t)TT*HIDD;         // EE*TT*HIDD
static const size_t B_TOTAL = BO_UPB  + (size_t)EE*TT*HIDD;
__device__ __nv_bfloat16 g_bh[B_TOTAL];
__device__ __nv_bfloat16 g_bl[B_TOTAL];

static const size_t CONV_TOTAL = BO_H;   // 46137344 elements of weights

// ---------------- int scratch ----------------
static const size_t IOFF_SLOT    = 0;                       // EE*TT
static const size_t IOFF_TOKSLOT = IOFF_SLOT + EE*TT;       // TT*KSEL
static const size_t IOFF_TOPI    = IOFF_TOKSLOT + TT*KSEL;  // TT*KSEL
static const size_t IOFF_CNT     = IOFF_TOPI + TT*KSEL;     // EE
__device__ int g_i[IOFF_CNT + EE];

// ---------------- helpers ----------------
__device__ __forceinline__ float gelu_tanh(float x) {
    float z = 0.7978845608028654f * (x + 0.044715f * x * x * x);
    float e = __expf(2.f * z);
    float th = 1.f - 2.f / (e + 1.f);
    return 0.5f * x * (1.f + th);
}

__device__ __forceinline__ void mma_bf16(float* d, const uint32_t* a, const uint32_t* b) {
    asm volatile(
        "mma.sync.aligned.m16n8k16.row.col.f32.bf16.bf16.f32 "
        "{%0,%1,%2,%3}, {%4,%5,%6,%7}, {%8,%9}, {%0,%1,%2,%3};\n"
        : "+f"(d[0]), "+f"(d[1]), "+f"(d[2]), "+f"(d[3])
        : "r"(a[0]), "r"(a[1]), "r"(a[2]), "r"(a[3]), "r"(b[0]), "r"(b[1]));
}

__device__ __forceinline__ void ldsm4(uint32_t* r, uint32_t addr) {
    asm volatile("ldmatrix.sync.aligned.m8n8.x4.shared.b16 {%0,%1,%2,%3}, [%4];"
                 : "=r"(r[0]), "=r"(r[1]), "=r"(r[2]), "=r"(r[3]) : "r"(addr));
}

__device__ __forceinline__ void split2(float x, float y, uint32_t& hi, uint32_t& lo) {
    __nv_bfloat16 hx = __float2bfloat16_rn(x);
    __nv_bfloat16 hy = __float2bfloat16_rn(y);
    __nv_bfloat16 lx = __float2bfloat16_rn(x - __bfloat162float(hx));
    __nv_bfloat16 ly = __float2bfloat16_rn(y - __bfloat162float(hy));
    __nv_bfloat162 h2 = __nv_bfloat162(hx, hy);
    __nv_bfloat162 l2 = __nv_bfloat162(lx, ly);
    hi = *reinterpret_cast<uint32_t*>(&h2);
    lo = *reinterpret_cast<uint32_t*>(&l2);
}

__device__ __forceinline__ void cpa16(uint32_t dst, const void* src, int srcbytes) {
    asm volatile("cp.async.cg.shared.global [%0], [%1], 16, %2;"
                 :: "r"(dst), "l"(src), "r"(srcbytes));
}
__device__ __forceinline__ void cpa_commit() { asm volatile("cp.async.commit_group;"); }
__device__ __forceinline__ void cpa_wait_all() { asm volatile("cp.async.wait_group 0;"); }

// ---------------- fused fp32 -> bf16 hi/lo convert for ALL weights ------------
struct ConvSrcs { const float* p[6]; };
__global__ void conv_all_kernel(ConvSrcs srcs, __nv_bfloat16* __restrict__ hi,
                                __nv_bfloat16* __restrict__ lo) {
    size_t i = ((size_t)blockIdx.x * blockDim.x + threadIdx.x) * 4;
    if (i >= CONV_TOTAL) return;
    // segment prefix sums (elements) — match BO_* layout exactly
    const size_t pf0 = 0;
    const size_t pf1 = (size_t)3 * DD * DD;
    const size_t pf2 = pf1 + (size_t)DD * DD;
    const size_t pf3 = pf2 + (size_t)EE * HIDD * DD;
    const size_t pf4 = pf3 + (size_t)EE * DD * HIDD;
    const size_t pf5 = pf4 + (size_t)HIDD * DD;
    int s; size_t base;
    if      (i < pf1) { s = 0; base = pf0; }
    else if (i < pf2) { s = 1; base = pf1; }
    else if (i < pf3) { s = 2; base = pf2; }
    else if (i < pf4) { s = 3; base = pf3; }
    else if (i < pf5) { s = 4; base = pf4; }
    else              { s = 5; base = pf5; }
    float4 v = *(const float4*)(srcs.p[s] + (i - base));
    uint32_t h0, l0, h1, l1;
    split2(v.x, v.y, h0, l0);
    split2(v.z, v.w, h1, l1);
    *(uint32_t*)(hi + i)     = h0;
    *(uint32_t*)(hi + i + 2) = h1;
    *(uint32_t*)(lo + i)     = l0;
    *(uint32_t*)(lo + i + 2) = l1;
}

// ---------------- LayerNorm ----------------
template <int MODE>
__global__ void ln_kernel(const float* __restrict__ x, const float* __restrict__ g,
                          const float* __restrict__ b, float* __restrict__ outf,
                          __nv_bfloat16* __restrict__ ohi, __nv_bfloat16* __restrict__ olo) {
    int t = blockIdx.x, tid = threadIdx.x;
    const float* xr = x + (size_t)t * DD;
    float v[4], s = 0.f, sq = 0.f;
#pragma unroll
    for (int k = 0; k < 4; k++) {
        v[k] = xr[tid + k * 256];
        s += v[k]; sq += v[k] * v[k];
    }
    __shared__ float rs[256], rq[256];
    rs[tid] = s; rq[tid] = sq;
    __syncthreads();
    for (int o = 128; o > 0; o >>= 1) {
        if (tid < o) { rs[tid] += rs[tid + o]; rq[tid] += rq[tid + o]; }
        __syncthreads();
    }
    float mean = rs[0] * (1.f / DD);
    float var  = rq[0] * (1.f / DD) - mean * mean;
    float inv  = rsqrtf(var + 1e-5f);
#pragma unroll
    for (int k = 0; k < 4; k++) {
        int d = tid + k * 256;
        float val = (v[k] - mean) * inv * g[d] + b[d];
        if (MODE == 1) outf[(size_t)t * DD + d] = val;
        __nv_bfloat16 hx = __float2bfloat16_rn(val);
        __nv_bfloat16 lx = __float2bfloat16_rn(val - __bfloat162float(hx));
        ohi[(size_t)t * DD + d] = hx;
        olo[(size_t)t * DD + d] = lx;
    }
}

// ---------------- tensor-core NT GEMM, split-bf16 planes ----------------------
// (unchanged from 3844us baseline)
#define LDAH 40            // smem row pitch in halves
#define ARR_B   10240      // one plane: 128 rows * 80B
#define STAGE_B 40960      // 4 planes
#define SMEM_GEMM 81920    // 2 stages
template <int EPI>
__global__ void __launch_bounds__(128) hgemm_nt(
    const __nv_bfloat16* __restrict__ Ahi, const __nv_bfloat16* __restrict__ Alo,
    const __nv_bfloat16* __restrict__ Bhi, const __nv_bfloat16* __restrict__ Blo,
    const float* __restrict__ bias, const float* __restrict__ resid,
    float* __restrict__ Cf, __nv_bfloat16* __restrict__ Chi, __nv_bfloat16* __restrict__ Clo,
    int M, int N, int Kd,
    const int* __restrict__ rowIdx, const int* __restrict__ cnt,
    size_t aZ, size_t bZ, size_t biasZ, size_t cZ, size_t idxZ) {
    int z = blockIdx.z;
    Ahi += (size_t)z * aZ; Alo += (size_t)z * aZ;
    Bhi += (size_t)z * bZ; Blo += (size_t)z * bZ;
    bias += (size_t)z * biasZ;
    if (EPI == 1) { Chi += (size_t)z * cZ; Clo += (size_t)z * cZ; }
    else          { Cf  += (size_t)z * cZ; }
    if (rowIdx) rowIdx += (size_t)z * idxZ;
    if (cnt) M = cnt[z];
    int mBase = blockIdx.y * 128;
    if (mBase >= M) return;
    int n0 = blockIdx.x * 128;

    extern __shared__ __align__(16) uint16_t smem_dyn[];
    uint32_t smemBase = (uint32_t)__cvta_generic_to_shared(smem_dyn);

    int tid = threadIdx.x;
    int wid = tid >> 5, lane = tid & 31;
    int warp_m = (wid & 1) * 64;
    int warp_n = (wid >> 1) * 64;

    ptrdiff_t dAlo = Alo - Ahi;
    ptrdiff_t dBlo = Blo - Bhi;
    int rowB0 = tid >> 2;
    int kh0   = (tid & 3) * 8;
    const __nv_bfloat16* aHiP[4];
    int aOK[4];
    uint32_t sOff[4];
#pragma unroll
    for (int i = 0; i < 4; i++) {
        int row = rowB0 + 32 * i;
        sOff[i] = (uint32_t)(row * LDAH + kh0) * 2;
        int gmr = mBase + row;
        bool ok = gmr < M;
        int sr = ok ? (rowIdx ? rowIdx[gmr] : gmr) : 0;
        aHiP[i] = Ahi + (size_t)sr * Kd + kh0;
        aOK[i] = ok ? 16 : 0;
    }
    const __nv_bfloat16* bHi0 = Bhi + (size_t)(n0 + rowB0) * Kd + kh0;

    uint32_t aOff[4];
#pragma unroll
    for (int mt = 0; mt < 4; mt++) {
        int row = warp_m + mt * 16 + (lane & 15);
        int colh = (lane >> 4) * 8;
        aOff[mt] = (uint32_t)(row * LDAH + colh) * 2;
    }
    uint32_t bOff[4];
#pragma unroll
    for (int np = 0; np < 4; np++) {
        int row = warp_n + np * 16 + (lane & 7) + ((lane >> 4) << 3);
        int colh = ((lane >> 3) & 1) * 8;
        bOff[np] = (uint32_t)(row * LDAH + colh) * 2;
    }

    float c[4][8][4];
#pragma unroll
    for (int i = 0; i < 4; i++)
#pragma unroll
        for (int j = 0; j < 8; j++)
#pragma unroll
            for (int k = 0; k < 4; k++) c[i][j][k] = 0.f;

    int nK = Kd >> 5;

    {
        uint32_t sb = smemBase;
#pragma unroll
        for (int i = 0; i < 4; i++) {
            const __nv_bfloat16* bp = bHi0 + (size_t)(32 * i) * Kd;
            cpa16(sb + sOff[i],             aHiP[i], aOK[i]);
            cpa16(sb + ARR_B + sOff[i],     aHiP[i] + dAlo, aOK[i]);
            cpa16(sb + 2 * ARR_B + sOff[i], bp, 16);
            cpa16(sb + 3 * ARR_B + sOff[i], bp + dBlo, 16);
        }
        cpa_commit();
    }

    for (int kt = 0; kt < nK; kt++) {
        int cur = kt & 1;
        cpa_wait_all();
        __syncthreads();
        if (kt + 1 < nK) {
            uint32_t sb = smemBase + (cur ^ 1) * STAGE_B;
            int koff = (kt + 1) * 32;
#pragma unroll
            for (int i = 0; i < 4; i++) {
                const __nv_bfloat16* bp = bHi0 + (size_t)(32 * i) * Kd + koff;
                cpa16(sb + sOff[i],             aHiP[i] + koff, aOK[i]);
                cpa16(sb + ARR_B + sOff[i],     aHiP[i] + dAlo + koff, aOK[i]);
                cpa16(sb + 2 * ARR_B + sOff[i], bp, 16);
                cpa16(sb + 3 * ARR_B + sOff[i], bp + dBlo, 16);
            }
            cpa_commit();
        }
        uint32_t stageB = smemBase + cur * STAGE_B;
#pragma unroll
        for (int ks = 0; ks < 2; ks++) {
            uint32_t kb = ks * 32;
            uint32_t ah[4][4], al[4][4], bh[8][2], bl[8][2];
#pragma unroll
            for (int mt = 0; mt < 4; mt++) {
                ldsm4(ah[mt], stageB + aOff[mt] + kb);
                ldsm4(al[mt], stageB + ARR_B + aOff[mt] + kb);
            }
#pragma unroll
            for (int np = 0; np < 4; np++) {
                uint32_t r[4];
                ldsm4(r, stageB + 2 * ARR_B + bOff[np] + kb);
                bh[2 * np][0] = r[0]; bh[2 * np][1] = r[1];
                bh[2 * np + 1][0] = r[2]; bh[2 * np + 1][1] = r[3];
                ldsm4(r, stageB + 3 * ARR_B + bOff[np] + kb);
                bl[2 * np][0] = r[0]; bl[2 * np][1] = r[1];
                bl[2 * np + 1][0] = r[2]; bl[2 * np + 1][1] = r[3];
            }
#pragma unroll
            for (int mt = 0; mt < 4; mt++)
#pragma unroll
                for (int nt = 0; nt < 8; nt++) {
                    mma_bf16(c[mt][nt], ah[mt], bh[nt]);
                    mma_bf16(c[mt][nt], ah[mt], bl[nt]);
                    mma_bf16(c[mt][nt], al[mt], bh[nt]);
                }
        }
    }

#pragma unroll
    for (int mt = 0; mt < 4; mt++) {
#pragma unroll
        for (int nt = 0; nt < 8; nt++) {
            int col = n0 + warp_n + nt * 8 + (lane & 3) * 2;
            float2 bb = *(const float2*)(bias + col);
#pragma unroll
            for (int half = 0; half < 2; half++) {
                int r = mBase + warp_m + mt * 16 + (lane >> 2) + half * 8;
                if (r >= M) continue;
                float v0 = c[mt][nt][half * 2 + 0] + bb.x;
                float v1 = c[mt][nt][half * 2 + 1] + bb.y;
                if (EPI == 1) {
                    v0 = gelu_tanh(v0); v1 = gelu_tanh(v1);
                    uint32_t hi, lo;
                    split2(v0, v1, hi, lo);
                    *(uint32_t*)(Chi + (size_t)r * N + col) = hi;
                    *(uint32_t*)(Clo + (size_t)r * N + col) = lo;
                } else {
                    if (EPI == 2) {
                        float2 rr = *(const float2*)(resid + (size_t)r * N + col);
                        v0 += rr.x; v1 += rr.y;
                    }
                    *(float2*)(Cf + (size_t)r * N + col) = make_float2(v0, v1);
                }
            }
        }
    }
}

// ---------------- causal flash attention: 2 queries/warp, 8 warps -------------
__global__ void __launch_bounds__(256) attn_kernel(const float* __restrict__ qkv,
                                                   __nv_bfloat16* __restrict__ ohi,
                                                   __nv_bfloat16* __restrict__ olo) {
    __shared__ float q_s[16][64];
    __shared__ float k_s[32][65];
    __shared__ float v_s[32][64];
    int bh = blockIdx.y;
    int b = bh >> 4, h = bh & 15;
    int q0 = blockIdx.x * 16;
    int tid = threadIdx.x;
    int w = tid >> 5, lane = tid & 31;

    {   // load 16 queries (scaled), 4 floats/thread
        int i = tid * 4;
        int qi = i >> 6, d = i & 63;
        const float* src = qkv + ((size_t)(b * SS + q0 + qi)) * (3 * DD) + h * 64 + d;
        float4 v = *(const float4*)src;
        q_s[qi][d]     = v.x * 0.125f;
        q_s[qi][d + 1] = v.y * 0.125f;
        q_s[qi][d + 2] = v.z * 0.125f;
        q_s[qi][d + 3] = v.w * 0.125f;
    }
    __syncthreads();
    float qa[64], qb[64];
#pragma unroll
    for (int d = 0; d < 64; d++) { qa[d] = q_s[2 * w][d]; qb[d] = q_s[2 * w + 1][d]; }

    int Qa = q0 + 2 * w, Qb = Qa + 1;
    float Ma = -1e30f, La = 0.f, oa0 = 0.f, oa1 = 0.f;
    float Mb = -1e30f, Lb = 0.f, ob0 = 0.f, ob1 = 0.f;
    int nkeys = q0 + 16;

    for (int t0 = 0; t0 < nkeys; t0 += 32) {
        __syncthreads();
        {   // cooperative K/V tile load (32x64 each), 8 floats/thread/array
            int r  = tid >> 3;
            int c8 = (tid & 7) * 8;
            int key = t0 + r;
            float4 k1 = make_float4(0, 0, 0, 0), k2 = k1, v1 = k1, v2 = k1;
            if (key < SS) {
                size_t base = ((size_t)(b * SS + key)) * (3 * DD) + h * 64 + c8;
                k1 = *(const float4*)(qkv + DD + base);
                k2 = *(const float4*)(qkv + DD + base + 4);
                v1 = *(const float4*)(qkv + 2 * DD + base);
                v2 = *(const float4*)(qkv + 2 * DD + base + 4);
            }
            k_s[r][c8 + 0] = k1.x; k_s[r][c8 + 1] = k1.y;
            k_s[r][c8 + 2] = k1.z; k_s[r][c8 + 3] = k1.w;
            k_s[r][c8 + 4] = k2.x; k_s[r][c8 + 5] = k2.y;
            k_s[r][c8 + 6] = k2.z; k_s[r][c8 + 7] = k2.w;
            *(float4*)&v_s[r][c8]     = v1;
            *(float4*)&v_s[r][c8 + 4] = v2;
        }
        __syncthreads();

        int key = t0 + lane;
        float aa = 0.f, ab = 0.f;
#pragma unroll
        for (int d = 0; d < 64; d++) {
            float kv = k_s[lane][d];
            aa += qa[d] * kv;
            ab += qb[d] * kv;
        }
        float sa = (key <= Qa) ? aa : -1e30f;
        float sb = (key <= Qb) ? ab : -1e30f;

        float ma = sa, mb = sb;
#pragma unroll
        for (int off = 16; off > 0; off >>= 1) {
            ma = fmaxf(ma, __shfl_xor_sync(0xffffffffu, ma, off));
            mb = fmaxf(mb, __shfl_xor_sync(0xffffffffu, mb, off));
        }
        if (ma > Ma) {
            float sc = __expf(Ma - ma);
            oa0 *= sc; oa1 *= sc; La *= sc;
            Ma = ma;
        }
        if (mb > Mb) {
            float sc = __expf(Mb - mb);
            ob0 *= sc; ob1 *= sc; Lb *= sc;
            Mb = mb;
        }
        float pa = (key <= Qa) ? __expf(sa - Ma) : 0.f;
        float pb = (key <= Qb) ? __expf(sb - Mb) : 0.f;
        float la = pa, lb = pb;
#pragma unroll
        for (int off = 16; off > 0; off >>= 1) {
            la += __shfl_xor_sync(0xffffffffu, la, off);
            lb += __shfl_xor_sync(0xffffffffu, lb, off);
        }
        La += la; Lb += lb;
#pragma unroll
        for (int j = 0; j < 32; j++) {
            float paj = __shfl_sync(0xffffffffu, pa, j);
            float pbj = __shfl_sync(0xffffffffu, pb, j);
            float2 vv = *(const float2*)&v_s[j][lane * 2];
            oa0 += paj * vv.x; oa1 += paj * vv.y;
            ob0 += pbj * vv.x; ob1 += pbj * vv.y;
        }
    }
    {
        float inv = 1.f / La;
        uint32_t hi, lo;
        split2(oa0 * inv, oa1 * inv, hi, lo);
        size_t off = ((size_t)(b * SS + Qa)) * DD + h * 64 + lane * 2;
        *(uint32_t*)(ohi + off) = hi;
        *(uint32_t*)(olo + off) = lo;
    }
    {
        float inv = 1.f / Lb;
        uint32_t hi, lo;
        split2(ob0 * inv, ob1 * inv, hi, lo);
        size_t off = ((size_t)(b * SS + Qb)) * DD + h * 64 + lane * 2;
        *(uint32_t*)(ohi + off) = hi;
        *(uint32_t*)(olo + off) = lo;
    }
}

// ---------------- MoE router ----------------
__global__ void router_kernel(const float* __restrict__ h2, const float* __restrict__ Wg,
                              float* __restrict__ probs, float* __restrict__ topw,
                              int* __restrict__ topi, int* __restrict__ slot_tok,
                              int* __restrict__ tok_slot, int* __restrict__ cnt) {
    int t = blockIdx.x, tid = threadIdx.x;  // 128 threads
    const float* hr = h2 + (size_t)t * DD;
    float a0 = 0, a1 = 0, a2 = 0, a3 = 0;
    for (int d = tid; d < DD; d += 128) {
        float hv = hr[d];
        a0 += hv * Wg[d];
        a1 += hv * Wg[DD + d];
        a2 += hv * Wg[2 * DD + d];
        a3 += hv * Wg[3 * DD + d];
    }
    __shared__ float r[4][128];
    r[0][tid] = a0; r[1][tid] = a1; r[2][tid] = a2; r[3][tid] = a3;
    __syncthreads();
    for (int o = 64; o > 0; o >>= 1) {
        if (tid < o) {
#pragma unroll
            for (int e = 0; e < 4; e++) r[e][tid] += r[e][tid + o];
        }
        __syncthreads();
    }
    if (tid == 0) {
        float l[4] = {r[0][0], r[1][0], r[2][0], r[3][0]};
        float m = fmaxf(fmaxf(l[0], l[1]), fmaxf(l[2], l[3]));
        float p[4], sum = 0.f;
#pragma unroll
        for (int e = 0; e < 4; e++) { p[e] = __expf(l[e] - m); sum += p[e]; }
#pragma unroll
        for (int e = 0; e < 4; e++) { p[e] /= sum; probs[t * 4 + e] = p[e]; }
        int i0 = 0;
#pragma unroll
        for (int e = 1; e < 4; e++) if (p[e] > p[i0]) i0 = e;
        int i1 = -1;
#pragma unroll
        for (int e = 0; e < 4; e++)
            if (e != i0 && (i1 < 0 || p[e] > p[i1])) i1 = e;
        float w0 = p[i0], w1 = p[i1], ws = w0 + w1;
        w0 /= ws; w1 /= ws;
        int pos0 = atomicAdd(&cnt[i0], 1);
        slot_tok[i0 * TT + pos0] = t;
        tok_slot[t * 2]     = i0 * TT + pos0;
        int pos1 = atomicAdd(&cnt[i1], 1);
        slot_tok[i1 * TT + pos1] = t;
        tok_slot[t * 2 + 1] = i1 * TT + pos1;
        topw[t * 2] = w0; topw[t * 2 + 1] = w1;
        topi[t * 2] = i0; topi[t * 2 + 1] = i1;
    }
}

// ---------------- aux loss ----------------
__global__ void aux_kernel(const float* __restrict__ probs, const int* __restrict__ topi,
                           float* __restrict__ auxout) {
    int tid = threadIdx.x;  // 512
    float ps[4] = {0, 0, 0, 0};
    float cs[4] = {0, 0, 0, 0};
    for (int t = tid; t < TT; t += 512) {
#pragma unroll
        for (int e = 0; e < 4; e++) ps[e] += probs[t * 4 + e];
        cs[topi[t * 2]] += 1.f;
        cs[topi[t * 2 + 1]] += 1.f;
    }
    __shared__ float sp[4][512], sc[4][512];
#pragma unroll
    for (int e = 0; e < 4; e++) { sp[e][tid] = ps[e]; sc[e][tid] = cs[e]; }
    __syncthreads();
    for (int o = 256; o > 0; o >>= 1) {
        if (tid < o) {
#pragma unroll
            for (int e = 0; e < 4; e++) {
                sp[e][tid] += sp[e][tid + o];
                sc[e][tid] += sc[e][tid + o];
            }
        }
        __syncthreads();
    }
    if (tid == 0) {
        float aux = 0.f;
#pragma unroll
        for (int e = 0; e < 4; e++) {
            float fi = sc[e][0] / (float)(TT * KSEL);
            float Pi = sp[e][0] / (float)TT;
            aux += fi * Pi;
        }
        auxout[0] = 0.01f * (float)EE * aux;
    }
}

// ---------------- final combine (scalar stores) ----------------
__global__ void combine_kernel(const float* __restrict__ x1, const float* __restrict__ sdown,
                               const float* __restrict__ eo, const float* __restrict__ topw,
                               const int* __restrict__ tok_slot, float* __restrict__ xout) {
    int t = blockIdx.x, tid = threadIdx.x;
    int c = tid * 4;
    int s0 = tok_slot[t * 2], s1 = tok_slot[t * 2 + 1];
    float w0 = topw[t * 2], w1 = topw[t * 2 + 1];
    float4 a  = *(const float4*)(x1 + (size_t)t * DD + c);
    float4 sd = *(const float4*)(sdown + (size_t)t * DD + c);
    float4 e0 = *(const float4*)(eo + (size_t)s0 * DD + c);
    float4 e1 = *(const float4*)(eo + (size_t)s1 * DD + c);
    float* o = xout + (size_t)t * DD + c;
    o[0] = a.x + sd.x + w0 * e0.x + w1 * e1.x;
    o[1] = a.y + sd.y + w0 * e0.y + w1 * e1.y;
    o[2] = a.z + sd.z + w0 * e0.z + w1 * e1.z;
    o[3] = a.w + sd.w + w0 * e0.w + w1 * e1.w;
}

// ---------------- launch ------------------------------------------------------
extern "C" void kernel_launch(void* const* d_in, const int* in_sizes, int n_in,
                              void* d_out, int out_size) {
    const float* x      = (const float*)d_in[0];
    const float* ln1_g  = (const float*)d_in[1];
    const float* ln1_b  = (const float*)d_in[2];
    const float* Wqkv   = (const float*)d_in[3];
    const float* bqkv   = (const float*)d_in[4];
    const float* Wo     = (const float*)d_in[5];
    const float* bo     = (const float*)d_in[6];
    const float* ln2_g  = (const float*)d_in[7];
    const float* ln2_b  = (const float*)d_in[8];
    const float* Wg     = (const float*)d_in[9];
    const float* We_up  = (const float*)d_in[10];
    const float* be_up  = (const float*)d_in[11];
    const float* We_dn  = (const float*)d_in[12];
    const float* be_dn  = (const float*)d_in[13];
    const float* Ws_up  = (const float*)d_in[14];
    const float* bs_up  = (const float*)d_in[15];
    const float* Ws_dn  = (const float*)d_in[16];
    const float* bs_dn  = (const float*)d_in[17];

    float* F = nullptr; int* I = nullptr;
    __nv_bfloat16* BH = nullptr; __nv_bfloat16* BL = nullptr;
    cudaGetSymbolAddress((void**)&F, g_f);
    cudaGetSymbolAddress((void**)&I, g_i);
    cudaGetSymbolAddress((void**)&BH, g_bh);
    cudaGetSymbolAddress((void**)&BL, g_bl);

    static bool attr_done = false;
    if (!attr_done) {
        cudaFuncSetAttribute(hgemm_nt<0>, cudaFuncAttributeMaxDynamicSharedMemorySize, SMEM_GEMM);
        cudaFuncSetAttribute(hgemm_nt<1>, cudaFuncAttributeMaxDynamicSharedMemorySize, SMEM_GEMM);
        cudaFuncSetAttribute(hgemm_nt<2>, cudaFuncAttributeMaxDynamicSharedMemorySize, SMEM_GEMM);
        attr_done = true;
    }

    float* qkv   = F + OFF_QKV;
    float* x1    = F + OFF_X1;
    float* h2f   = F + OFF_H2F;
    float* sdown = F + OFF_SDOWN;
    float* eob   = F + OFF_EO;
    float* probs = F + OFF_PROBS;
    float* topw  = F + OFF_TOPW;
    int* slot_tok = I + IOFF_SLOT;
    int* tok_slot = I + IOFF_TOKSLOT;
    int* topi     = I + IOFF_TOPI;
    int* cnt      = I + IOFF_CNT;

    float* outp = (float*)d_out;
    float* auxp = nullptr;
    float* xout = outp;
    if (out_size == TT * DD + 1) { auxp = outp; xout = outp + 1; }

    cudaMemsetAsync(cnt, 0, EE * sizeof(int));

    // 0) ALL weight conversions in one fused kernel
    {
        ConvSrcs cs;
        cs.p[0] = Wqkv; cs.p[1] = Wo; cs.p[2] = We_up;
        cs.p[3] = We_dn; cs.p[4] = Ws_up; cs.p[5] = Ws_dn;
        int nblk = (int)((CONV_TOTAL / 4 + 255) / 256);
        conv_all_kernel<<<nblk, 256>>>(cs, BH, BL);
    }

    // 1) LN1 -> bf16 planes
    ln_kernel<0><<<TT, 256>>>(x, ln1_g, ln1_b, nullptr, BH + BO_H, BL + BO_H);
    // 2) QKV projection
    hgemm_nt<0><<<dim3(24, 32, 1), 128, SMEM_GEMM>>>(
        BH + BO_H, BL + BO_H, BH + BO_WQKV, BL + BO_WQKV, bqkv, nullptr,
        qkv, nullptr, nullptr, TT, 3 * DD, DD, nullptr, nullptr, 0, 0, 0, 0, 0);
    // 3) causal attention -> bf16 planes
    attn_kernel<<<dim3(SS / 16, Bb * HH), 256>>>(qkv, BH + BO_ATTN, BL + BO_ATTN);
    // 4) output proj + residual -> x1 fp32
    hgemm_nt<2><<<dim3(8, 32, 1), 128, SMEM_GEMM>>>(
        BH + BO_ATTN, BL + BO_ATTN, BH + BO_WO, BL + BO_WO, bo, x,
        x1, nullptr, nullptr, TT, DD, DD, nullptr, nullptr, 0, 0, 0, 0, 0);
    // 5) LN2 -> fp32 + bf16 planes
    ln_kernel<1><<<TT, 256>>>(x1, ln2_g, ln2_b, h2f, BH + BO_H2, BL + BO_H2);
    // 6) router
    router_kernel<<<TT, 128>>>(h2f, Wg, probs, topw, topi, slot_tok, tok_slot, cnt);
    // 7) aux loss
    if (auxp) aux_kernel<<<1, 512>>>(probs, topi, auxp);
    // 8) expert up (gathered, gelu -> bf16 planes)
    hgemm_nt<1><<<dim3(32, 32, 4), 128, SMEM_GEMM>>>(
        BH + BO_H2, BL + BO_H2, BH + BO_WEUP, BL + BO_WEUP, be_up, nullptr,
        nullptr, BH + BO_UPB, BL + BO_UPB, TT, HIDD, DD, slot_tok, cnt,
        0, (size_t)HIDD * DD, (size_t)HIDD, (size_t)TT * HIDD, (size_t)TT);
    // 9) expert down -> eob fp32
    hgemm_nt<0><<<dim3(8, 32, 4), 128, SMEM_GEMM>>>(
        BH + BO_UPB, BL + BO_UPB, BH + BO_WEDN, BL + BO_WEDN, be_dn, nullptr,
        eob, nullptr, nullptr, TT, DD, HIDD, nullptr, cnt,
        (size_t)TT * HIDD, (size_t)DD * HIDD, (size_t)DD, (size_t)TT * DD, 0);
    // 10) shared expert up (gelu -> bf16 planes)
    hgemm_nt<1><<<dim3(32, 32, 1), 128, SMEM_GEMM>>>(
        BH + BO_H2, BL + BO_H2, BH + BO_WSUP, BL + BO_WSUP, bs_up, nullptr,
        nullptr, BH + BO_SUP, BL + BO_SUP, TT, HIDD, DD, nullptr, nullptr, 0, 0, 0, 0, 0);
    // 11) shared expert down -> sdown fp32
    hgemm_nt<0><<<dim3(8, 32, 1), 128, SMEM_GEMM>>>(
        BH + BO_SUP, BL + BO_SUP, BH + BO_WSDN, BL + BO_WSDN, bs_dn, nullptr,
        sdown, nullptr, nullptr, TT, DD, HIDD, nullptr, nullptr, 0, 0, 0, 0, 0);
    // 12) combine
    combine_kernel<<<TT, 256>>>(x1, sdown, eob, topw, tok_slot, xout);
}

// round 15
// speedup vs baseline: 2.5633x; 1.3636x over previous
#include <cuda_runtime.h>
#include <cuda_bf16.h>
#include <math.h>
#include <stdint.h>

// ---------------- problem constants ----------------
#define Bb   2
#define SS   2048
#define DD   1024
#define HH   16
#define HDIM 64
#define EE   4
#define KSEL 2
#define HIDD 4096
#define TT   (Bb*SS)   // 4096 tokens

// ---------------- fp32 scratch ----------------
static const size_t OFF_X1    = 0;                                   // TT*DD
static const size_t OFF_H2F   = OFF_X1    + (size_t)TT*DD;           // TT*DD
static const size_t OFF_SDOWN = OFF_H2F   + (size_t)TT*DD;           // TT*DD
static const size_t OFF_EO    = OFF_SDOWN + (size_t)TT*DD;           // EE*TT*DD
static const size_t OFF_PROBS = OFF_EO    + (size_t)EE*TT*DD;        // TT*EE
static const size_t OFF_TOPW  = OFF_PROBS + (size_t)TT*EE;           // TT*KSEL
static const size_t F_TOTAL   = OFF_TOPW  + (size_t)TT*KSEL;
__device__ float g_f[F_TOTAL];

// ---------------- bf16 hi/lo planes (weights contiguous & in conv order) ------
static const size_t BO_WQKV = 0;                                 // 3*DD*DD
static const size_t BO_WO   = BO_WQKV + (size_t)3*DD*DD;         // DD*DD
static const size_t BO_WEUP = BO_WO   + (size_t)DD*DD;           // EE*HIDD*DD
static const size_t BO_WEDN = BO_WEUP + (size_t)EE*HIDD*DD;      // EE*DD*HIDD
static const size_t BO_WSUP = BO_WEDN + (size_t)EE*DD*HIDD;      // HIDD*DD
static const size_t BO_WSDN = BO_WSUP + (size_t)HIDD*DD;         // DD*HIDD
static const size_t BO_H    = BO_WSDN + (size_t)DD*HIDD;         // TT*DD
static const size_t BO_ATTN = BO_H    + (size_t)TT*DD;           // TT*DD
static const size_t BO_H2   = BO_ATTN + (size_t)TT*DD;           // TT*DD
static const size_t BO_SUP  = BO_H2   + (size_t)TT*DD;           // TT*HIDD
static const size_t BO_UPB  = BO_SUP  + (size_t)TT*HIDD;         // EE*TT*HIDD
static const size_t BO_QKV  = BO_UPB  + (size_t)EE*TT*HIDD;      // TT*3*DD
static const size_t B_TOTAL = BO_QKV  + (size_t)TT*3*DD;
__device__ __nv_bfloat16 g_bh[B_TOTAL];
__device__ __nv_bfloat16 g_bl[B_TOTAL];

static const size_t CONV_TOTAL = BO_H;   // weights only

// ---------------- int scratch ----------------
static const size_t IOFF_SLOT    = 0;                       // EE*TT
static const size_t IOFF_TOKSLOT = IOFF_SLOT + EE*TT;       // TT*KSEL
static const size_t IOFF_TOPI    = IOFF_TOKSLOT + TT*KSEL;  // TT*KSEL
static const size_t IOFF_CNT     = IOFF_TOPI + TT*KSEL;     // EE
__device__ int g_i[IOFF_CNT + EE];

// ---------------- helpers ----------------
__device__ __forceinline__ float gelu_tanh(float x) {
    float z = 0.7978845608028654f * (x + 0.044715f * x * x * x);
    float e = __expf(2.f * z);
    float th = 1.f - 2.f / (e + 1.f);
    return 0.5f * x * (1.f + th);
}

__device__ __forceinline__ void mma_bf16(float* d, const uint32_t* a, const uint32_t* b) {
    asm volatile(
        "mma.sync.aligned.m16n8k16.row.col.f32.bf16.bf16.f32 "
        "{%0,%1,%2,%3}, {%4,%5,%6,%7}, {%8,%9}, {%0,%1,%2,%3};\n"
        : "+f"(d[0]), "+f"(d[1]), "+f"(d[2]), "+f"(d[3])
        : "r"(a[0]), "r"(a[1]), "r"(a[2]), "r"(a[3]), "r"(b[0]), "r"(b[1]));
}

__device__ __forceinline__ void ldsm4(uint32_t* r, uint32_t addr) {
    asm volatile("ldmatrix.sync.aligned.m8n8.x4.shared.b16 {%0,%1,%2,%3}, [%4];"
                 : "=r"(r[0]), "=r"(r[1]), "=r"(r[2]), "=r"(r[3]) : "r"(addr));
}

__device__ __forceinline__ void split2(float x, float y, uint32_t& hi, uint32_t& lo) {
    __nv_bfloat16 hx = __float2bfloat16_rn(x);
    __nv_bfloat16 hy = __float2bfloat16_rn(y);
    __nv_bfloat16 lx = __float2bfloat16_rn(x - __bfloat162float(hx));
    __nv_bfloat16 ly = __float2bfloat16_rn(y - __bfloat162float(hy));
    __nv_bfloat162 h2 = __nv_bfloat162(hx, hy);
    __nv_bfloat162 l2 = __nv_bfloat162(lx, ly);
    hi = *reinterpret_cast<uint32_t*>(&h2);
    lo = *reinterpret_cast<uint32_t*>(&l2);
}

__device__ __forceinline__ void cpa16(uint32_t dst, const void* src, int srcbytes) {
    asm volatile("cp.async.cg.shared.global [%0], [%1], 16, %2;"
                 :: "r"(dst), "l"(src), "r"(srcbytes));
}
__device__ __forceinline__ void cpa_commit() { asm volatile("cp.async.commit_group;"); }
__device__ __forceinline__ void cpa_wait_all() { asm volatile("cp.async.wait_group 0;"); }

// ---------------- fused fp32 -> bf16 hi/lo convert for ALL weights ------------
struct ConvSrcs { const float* p[6]; };
__global__ void conv_all_kernel(ConvSrcs srcs, __nv_bfloat16* __restrict__ hi,
                                __nv_bfloat16* __restrict__ lo) {
    size_t i = ((size_t)blockIdx.x * blockDim.x + threadIdx.x) * 4;
    if (i >= CONV_TOTAL) return;
    const size_t pf0 = 0;
    const size_t pf1 = (size_t)3 * DD * DD;
    const size_t pf2 = pf1 + (size_t)DD * DD;
    const size_t pf3 = pf2 + (size_t)EE * HIDD * DD;
    const size_t pf4 = pf3 + (size_t)EE * DD * HIDD;
    const size_t pf5 = pf4 + (size_t)HIDD * DD;
    int s; size_t base;
    if      (i < pf1) { s = 0; base = pf0; }
    else if (i < pf2) { s = 1; base = pf1; }
    else if (i < pf3) { s = 2; base = pf2; }
    else if (i < pf4) { s = 3; base = pf3; }
    else if (i < pf5) { s = 4; base = pf4; }
    else              { s = 5; base = pf5; }
    float4 v = *(const float4*)(srcs.p[s] + (i - base));
    uint32_t h0, l0, h1, l1;
    split2(v.x, v.y, h0, l0);
    split2(v.z, v.w, h1, l1);
    *(uint32_t*)(hi + i)     = h0;
    *(uint32_t*)(hi + i + 2) = h1;
    *(uint32_t*)(lo + i)     = l0;
    *(uint32_t*)(lo + i + 2) = l1;
}

// ---------------- LayerNorm ----------------
template <int MODE>
__global__ void ln_kernel(const float* __restrict__ x, const float* __restrict__ g,
                          const float* __restrict__ b, float* __restrict__ outf,
                          __nv_bfloat16* __restrict__ ohi, __nv_bfloat16* __restrict__ olo) {
    int t = blockIdx.x, tid = threadIdx.x;
    const float* xr = x + (size_t)t * DD;
    float v[4], s = 0.f, sq = 0.f;
#pragma unroll
    for (int k = 0; k < 4; k++) {
        v[k] = xr[tid + k * 256];
        s += v[k]; sq += v[k] * v[k];
    }
    __shared__ float rs[256], rq[256];
    rs[tid] = s; rq[tid] = sq;
    __syncthreads();
    for (int o = 128; o > 0; o >>= 1) {
        if (tid < o) { rs[tid] += rs[tid + o]; rq[tid] += rq[tid + o]; }
        __syncthreads();
    }
    float mean = rs[0] * (1.f / DD);
    float var  = rq[0] * (1.f / DD) - mean * mean;
    float inv  = rsqrtf(var + 1e-5f);
#pragma unroll
    for (int k = 0; k < 4; k++) {
        int d = tid + k * 256;
        float val = (v[k] - mean) * inv * g[d] + b[d];
        if (MODE == 1) outf[(size_t)t * DD + d] = val;
        __nv_bfloat16 hx = __float2bfloat16_rn(val);
        __nv_bfloat16 lx = __float2bfloat16_rn(val - __bfloat162float(hx));
        ohi[(size_t)t * DD + d] = hx;
        olo[(size_t)t * DD + d] = lx;
    }
}

// ---------------- tensor-core NT GEMM, split-bf16 planes ----------------------
// EPI: 0 fp32; 1 gelu->bf16 planes; 2 fp32+resid; 3 bf16 planes (no act)
#define LDAH 40            // smem row pitch in halves
#define ARR_B   10240      // one plane: 128 rows * 80B
#define STAGE_B 40960      // 4 planes
#define SMEM_GEMM 81920    // 2 stages
template <int EPI>
__global__ void __launch_bounds__(128) hgemm_nt(
    const __nv_bfloat16* __restrict__ Ahi, const __nv_bfloat16* __restrict__ Alo,
    const __nv_bfloat16* __restrict__ Bhi, const __nv_bfloat16* __restrict__ Blo,
    const float* __restrict__ bias, const float* __restrict__ resid,
    float* __restrict__ Cf, __nv_bfloat16* __restrict__ Chi, __nv_bfloat16* __restrict__ Clo,
    int M, int N, int Kd,
    const int* __restrict__ rowIdx, const int* __restrict__ cnt,
    size_t aZ, size_t bZ, size_t biasZ, size_t cZ, size_t idxZ) {
    int z = blockIdx.z;
    Ahi += (size_t)z * aZ; Alo += (size_t)z * aZ;
    Bhi += (size_t)z * bZ; Blo += (size_t)z * bZ;
    bias += (size_t)z * biasZ;
    if (EPI == 1 || EPI == 3) { Chi += (size_t)z * cZ; Clo += (size_t)z * cZ; }
    else                      { Cf  += (size_t)z * cZ; }
    if (rowIdx) rowIdx += (size_t)z * idxZ;
    if (cnt) M = cnt[z];
    int mBase = blockIdx.y * 128;
    if (mBase >= M) return;
    int n0 = blockIdx.x * 128;

    extern __shared__ __align__(16) uint16_t smem_dyn[];
    uint32_t smemBase = (uint32_t)__cvta_generic_to_shared(smem_dyn);

    int tid = threadIdx.x;
    int wid = tid >> 5, lane = tid & 31;
    int warp_m = (wid & 1) * 64;
    int warp_n = (wid >> 1) * 64;

    ptrdiff_t dAlo = Alo - Ahi;
    ptrdiff_t dBlo = Blo - Bhi;
    int rowB0 = tid >> 2;
    int kh0   = (tid & 3) * 8;
    const __nv_bfloat16* aHiP[4];
    int aOK[4];
    uint32_t sOff[4];
#pragma unroll
    for (int i = 0; i < 4; i++) {
        int row = rowB0 + 32 * i;
        sOff[i] = (uint32_t)(row * LDAH + kh0) * 2;
        int gmr = mBase + row;
        bool ok = gmr < M;
        int sr = ok ? (rowIdx ? rowIdx[gmr] : gmr) : 0;
        aHiP[i] = Ahi + (size_t)sr * Kd + kh0;
        aOK[i] = ok ? 16 : 0;
    }
    const __nv_bfloat16* bHi0 = Bhi + (size_t)(n0 + rowB0) * Kd + kh0;

    uint32_t aOff[4];
#pragma unroll
    for (int mt = 0; mt < 4; mt++) {
        int row = warp_m + mt * 16 + (lane & 15);
        int colh = (lane >> 4) * 8;
        aOff[mt] = (uint32_t)(row * LDAH + colh) * 2;
    }
    uint32_t bOff[4];
#pragma unroll
    for (int np = 0; np < 4; np++) {
        int row = warp_n + np * 16 + (lane & 7) + ((lane >> 4) << 3);
        int colh = ((lane >> 3) & 1) * 8;
        bOff[np] = (uint32_t)(row * LDAH + colh) * 2;
    }

    float c[4][8][4];
#pragma unroll
    for (int i = 0; i < 4; i++)
#pragma unroll
        for (int j = 0; j < 8; j++)
#pragma unroll
            for (int k = 0; k < 4; k++) c[i][j][k] = 0.f;

    int nK = Kd >> 5;

    {
        uint32_t sb = smemBase;
#pragma unroll
        for (int i = 0; i < 4; i++) {
            const __nv_bfloat16* bp = bHi0 + (size_t)(32 * i) * Kd;
            cpa16(sb + sOff[i],             aHiP[i], aOK[i]);
            cpa16(sb + ARR_B + sOff[i],     aHiP[i] + dAlo, aOK[i]);
            cpa16(sb + 2 * ARR_B + sOff[i], bp, 16);
            cpa16(sb + 3 * ARR_B + sOff[i], bp + dBlo, 16);
        }
        cpa_commit();
    }

    for (int kt = 0; kt < nK; kt++) {
        int cur = kt & 1;
        cpa_wait_all();
        __syncthreads();
        if (kt + 1 < nK) {
            uint32_t sb = smemBase + (cur ^ 1) * STAGE_B;
            int koff = (kt + 1) * 32;
#pragma unroll
            for (int i = 0; i < 4; i++) {
                const __nv_bfloat16* bp = bHi0 + (size_t)(32 * i) * Kd + koff;
                cpa16(sb + sOff[i],             aHiP[i] + koff, aOK[i]);
                cpa16(sb + ARR_B + sOff[i],     aHiP[i] + dAlo + koff, aOK[i]);
                cpa16(sb + 2 * ARR_B + sOff[i], bp, 16);
                cpa16(sb + 3 * ARR_B + sOff[i], bp + dBlo, 16);
            }
            cpa_commit();
        }
        uint32_t stageB = smemBase + cur * STAGE_B;
#pragma unroll
        for (int ks = 0; ks < 2; ks++) {
            uint32_t kb = ks * 32;
            uint32_t ah[4][4], al[4][4], bh[8][2], bl[8][2];
#pragma unroll
            for (int mt = 0; mt < 4; mt++) {
                ldsm4(ah[mt], stageB + aOff[mt] + kb);
                ldsm4(al[mt], stageB + ARR_B + aOff[mt] + kb);
            }
#pragma unroll
            for (int np = 0; np < 4; np++) {
                uint32_t r[4];
                ldsm4(r, stageB + 2 * ARR_B + bOff[np] + kb);
                bh[2 * np][0] = r[0]; bh[2 * np][1] = r[1];
                bh[2 * np + 1][0] = r[2]; bh[2 * np + 1][1] = r[3];
                ldsm4(r, stageB + 3 * ARR_B + bOff[np] + kb);
                bl[2 * np][0] = r[0]; bl[2 * np][1] = r[1];
                bl[2 * np + 1][0] = r[2]; bl[2 * np + 1][1] = r[3];
            }
#pragma unroll
            for (int mt = 0; mt < 4; mt++)
#pragma unroll
                for (int nt = 0; nt < 8; nt++) {
                    mma_bf16(c[mt][nt], ah[mt], bh[nt]);
                    mma_bf16(c[mt][nt], ah[mt], bl[nt]);
                    mma_bf16(c[mt][nt], al[mt], bh[nt]);
                }
        }
    }

#pragma unroll
    for (int mt = 0; mt < 4; mt++) {
#pragma unroll
        for (int nt = 0; nt < 8; nt++) {
            int col = n0 + warp_n + nt * 8 + (lane & 3) * 2;
            float2 bb = *(const float2*)(bias + col);
#pragma unroll
            for (int half = 0; half < 2; half++) {
                int r = mBase + warp_m + mt * 16 + (lane >> 2) + half * 8;
                if (r >= M) continue;
                float v0 = c[mt][nt][half * 2 + 0] + bb.x;
                float v1 = c[mt][nt][half * 2 + 1] + bb.y;
                if (EPI == 1 || EPI == 3) {
                    if (EPI == 1) { v0 = gelu_tanh(v0); v1 = gelu_tanh(v1); }
                    uint32_t hi, lo;
                    split2(v0, v1, hi, lo);
                    *(uint32_t*)(Chi + (size_t)r * N + col) = hi;
                    *(uint32_t*)(Clo + (size_t)r * N + col) = lo;
                } else {
                    if (EPI == 2) {
                        float2 rr = *(const float2*)(resid + (size_t)r * N + col);
                        v0 += rr.x; v1 += rr.y;
                    }
                    *(float2*)(Cf + (size_t)r * N + col) = make_float2(v0, v1);
                }
            }
        }
    }
}

// ---------------- tensor-core causal flash attention --------------------------
// CTA: 64 queries of one (b,h); 4 warps x 16 queries; key tiles of 64.
// Q/K/V from bf16 hi/lo qkv planes; O -> bf16 hi/lo attn planes.
#define APITCH 72   // smem row pitch in halves (conflict-free for ldmatrix)
__global__ void __launch_bounds__(128) attn_mma_kernel(
    const __nv_bfloat16* __restrict__ qh, const __nv_bfloat16* __restrict__ ql,
    __nv_bfloat16* __restrict__ ohi, __nv_bfloat16* __restrict__ olo) {
    __shared__ __align__(16) uint16_t sm[4 * 64 * APITCH];
    uint32_t smBase = (uint32_t)__cvta_generic_to_shared(sm);
    const uint32_t KHI = 0, KLO = 64 * APITCH * 2, VHI = 2 * KLO, VLO = 3 * KLO;

    int qblk = gridDim.x - 1 - blockIdx.x;   // heavy CTAs first
    int q0 = qblk * 64;
    int bh = blockIdx.y;
    int b = bh >> 4, h = bh & 15;
    int tid = threadIdx.x;
    int w = tid >> 5, lane = tid & 31;
    ptrdiff_t dlo = ql - qh;

    // ---- cooperative load mapping: seg -> (row, 8-half chunk) ----
    int lrow = tid >> 1;             // 0..63
    int lc8a = (tid & 1) * 16;       // chunk base; each thread does chunks {lc8a, lc8a+8} x ... 
    // simpler: 4 segs of (row, c8): seg = tid + i*128, row = seg>>3? 512 segs/128 thr = 4
    // (keep the seg scheme)
    (void)lrow; (void)lc8a;

    // ---- ldmatrix offsets (pitch APITCH) ----
    uint32_t aOff[4];   // Q A-frags: rows w*16 + (lane&15), col (lane>>4)*8 (+kk*16 halves)
#pragma unroll
    for (int kk = 0; kk < 4; kk++) {
        int row = w * 16 + (lane & 15);
        int colh = (lane >> 4) * 8 + kk * 16;
        aOff[kk] = (uint32_t)(row * APITCH + colh) * 2;
    }
    uint32_t bOff[4];   // B-frags: rows np*16 + (lane&7) + ((lane>>4)<<3), col ((lane>>3)&1)*8
#pragma unroll
    for (int np = 0; np < 4; np++) {
        int row = np * 16 + (lane & 7) + ((lane >> 4) << 3);
        int colh = ((lane >> 3) & 1) * 8;
        bOff[np] = (uint32_t)(row * APITCH + colh) * 2;
    }

    // ---- stage Q into K area, load A-frags ----
    const __nv_bfloat16* qbase = qh + (size_t)(b * SS + q0) * (3 * DD) + h * 64;
#pragma unroll
    for (int i = 0; i < 4; i++) {
        int seg = tid + i * 128;
        int row = seg >> 3, c8 = (seg & 7) * 8;
        const __nv_bfloat16* src = qbase + (size_t)row * (3 * DD) + c8;
        uint32_t doff = (uint32_t)(row * APITCH + c8) * 2;
        cpa16(smBase + KHI + doff, src, 16);
        cpa16(smBase + KLO + doff, src + dlo, 16);
    }
    cpa_commit();
    cpa_wait_all();
    __syncthreads();
    uint32_t Qh[4][4], Ql[4][4];
#pragma unroll
    for (int kk = 0; kk < 4; kk++) {
        ldsm4(Qh[kk], smBase + KHI + aOff[kk]);
        ldsm4(Ql[kk], smBase + KLO + aOff[kk]);
    }
    __syncthreads();

    float O[8][4];
#pragma unroll
    for (int i = 0; i < 8; i++)
#pragma unroll
        for (int j = 0; j < 4; j++) O[i][j] = 0.f;
    float m0 = -1e30f, m1 = -1e30f, l0 = 0.f, l1 = 0.f;

    int ntile = qblk + 1;
    const __nv_bfloat16* kvbase = qh + (size_t)(b * SS) * (3 * DD) + h * 64;

    for (int t = 0; t < ntile; t++) {
        int t0 = t * 64;
        // ---- load K (cp.async) + V (transpose scatter) ----
#pragma unroll
        for (int i = 0; i < 4; i++) {
            int seg = tid + i * 128;
            int row = seg >> 3, c8 = (seg & 7) * 8;
            const __nv_bfloat16* ks = kvbase + (size_t)(t0 + row) * (3 * DD) + DD + c8;
            uint32_t doff = (uint32_t)(row * APITCH + c8) * 2;
            cpa16(smBase + KHI + doff, ks, 16);
            cpa16(smBase + KLO + doff, ks + dlo, 16);
        }
        cpa_commit();
#pragma unroll
        for (int i = 0; i < 4; i++) {
            int seg = tid + i * 128;
            int row = seg >> 3, c8 = (seg & 7) * 8;
            const __nv_bfloat16* vs = kvbase + (size_t)(t0 + row) * (3 * DD) + 2 * DD + c8;
            uint4 vh4 = *(const uint4*)vs;
            uint4 vl4 = *(const uint4*)(vs + dlo);
            const uint16_t* hh = (const uint16_t*)&vh4;
            const uint16_t* ll = (const uint16_t*)&vl4;
            uint16_t* vtH = sm + 2 * 64 * APITCH;   // VHI in halves
            uint16_t* vtL = sm + 3 * 64 * APITCH;
#pragma unroll
            for (int j = 0; j < 8; j++) {
                vtH[(c8 + j) * APITCH + row] = hh[j];
                vtL[(c8 + j) * APITCH + row] = ll[j];
            }
        }
        cpa_wait_all();
        __syncthreads();

        // ---- scores S[16q x 64key] ----
        float s[8][4];
#pragma unroll
        for (int i = 0; i < 8; i++)
#pragma unroll
            for (int j = 0; j < 4; j++) s[i][j] = 0.f;
#pragma unroll
        for (int ks = 0; ks < 4; ks++) {
            uint32_t kb = ks * 32;
            uint32_t bhf[8][2], blf[8][2];
#pragma unroll
            for (int np = 0; np < 4; np++) {
                uint32_t r[4];
                ldsm4(r, smBase + KHI + bOff[np] + kb);
                bhf[2 * np][0] = r[0]; bhf[2 * np][1] = r[1];
                bhf[2 * np + 1][0] = r[2]; bhf[2 * np + 1][1] = r[3];
                ldsm4(r, smBase + KLO + bOff[np] + kb);
                blf[2 * np][0] = r[0]; blf[2 * np][1] = r[1];
                blf[2 * np + 1][0] = r[2]; blf[2 * np + 1][1] = r[3];
            }
#pragma unroll
            for (int nt = 0; nt < 8; nt++) {
                mma_bf16(s[nt], Qh[ks], bhf[nt]);
                mma_bf16(s[nt], Qh[ks], blf[nt]);
                mma_bf16(s[nt], Ql[ks], bhf[nt]);
            }
        }
        // scale + causal mask (diagonal tile only)
#pragma unroll
        for (int nt = 0; nt < 8; nt++)
#pragma unroll
            for (int e = 0; e < 4; e++) s[nt][e] *= 0.125f;
        if (t0 == q0) {
            int kc = (lane & 3) * 2;
            int qr = w * 16 + (lane >> 2);
#pragma unroll
            for (int nt = 0; nt < 8; nt++) {
                int keyb = nt * 8 + kc;
                if (keyb     > qr)     s[nt][0] = -1e30f;
                if (keyb + 1 > qr)     s[nt][1] = -1e30f;
                if (keyb     > qr + 8) s[nt][2] = -1e30f;
                if (keyb + 1 > qr + 8) s[nt][3] = -1e30f;
            }
        }
        // ---- online softmax ----
        float mt0 = -1e30f, mt1 = -1e30f;
#pragma unroll
        for (int nt = 0; nt < 8; nt++) {
            mt0 = fmaxf(mt0, fmaxf(s[nt][0], s[nt][1]));
            mt1 = fmaxf(mt1, fmaxf(s[nt][2], s[nt][3]));
        }
        mt0 = fmaxf(mt0, __shfl_xor_sync(0xffffffffu, mt0, 1));
        mt0 = fmaxf(mt0, __shfl_xor_sync(0xffffffffu, mt0, 2));
        mt1 = fmaxf(mt1, __shfl_xor_sync(0xffffffffu, mt1, 1));
        mt1 = fmaxf(mt1, __shfl_xor_sync(0xffffffffu, mt1, 2));
        float mn0 = fmaxf(m0, mt0), mn1 = fmaxf(m1, mt1);
        float f0 = __expf(m0 - mn0), f1 = __expf(m1 - mn1);
        m0 = mn0; m1 = mn1;
        l0 *= f0; l1 *= f1;
#pragma unroll
        for (int nd = 0; nd < 8; nd++) {
            O[nd][0] *= f0; O[nd][1] *= f0;
            O[nd][2] *= f1; O[nd][3] *= f1;
        }
        float ls0 = 0.f, ls1 = 0.f;
#pragma unroll
        for (int nt = 0; nt < 8; nt++) {
            s[nt][0] = __expf(s[nt][0] - m0);
            s[nt][1] = __expf(s[nt][1] - m0);
            s[nt][2] = __expf(s[nt][2] - m1);
            s[nt][3] = __expf(s[nt][3] - m1);
            ls0 += s[nt][0] + s[nt][1];
            ls1 += s[nt][2] + s[nt][3];
        }
        ls0 += __shfl_xor_sync(0xffffffffu, ls0, 1);
        ls0 += __shfl_xor_sync(0xffffffffu, ls0, 2);
        ls1 += __shfl_xor_sync(0xffffffffu, ls1, 1);
        ls1 += __shfl_xor_sync(0xffffffffu, ls1, 2);
        l0 += ls0; l1 += ls1;

        // ---- PV: O += P @ V  (A = P frags from s tiles, B = VT rows) ----
#pragma unroll
        for (int kk = 0; kk < 4; kk++) {
            uint32_t kb = kk * 32;
            uint32_t vh[8][2], vl[8][2];
#pragma unroll
            for (int np = 0; np < 4; np++) {
                uint32_t r[4];
                ldsm4(r, smBase + VHI + bOff[np] + kb);
                vh[2 * np][0] = r[0]; vh[2 * np][1] = r[1];
                vh[2 * np + 1][0] = r[2]; vh[2 * np + 1][1] = r[3];
                ldsm4(r, smBase + VLO + bOff[np] + kb);
                vl[2 * np][0] = r[0]; vl[2 * np][1] = r[1];
                vl[2 * np + 1][0] = r[2]; vl[2 * np + 1][1] = r[3];
            }
            uint32_t Pha[4], Pla[4];
            split2(s[2 * kk][0], s[2 * kk][1], Pha[0], Pla[0]);
            split2(s[2 * kk][2], s[2 * kk][3], Pha[1], Pla[1]);
            split2(s[2 * kk + 1][0], s[2 * kk + 1][1], Pha[2], Pla[2]);
            split2(s[2 * kk + 1][2], s[2 * kk + 1][3], Pha[3], Pla[3]);
#pragma unroll
            for (int nd = 0; nd < 8; nd++) {
                mma_bf16(O[nd], Pha, vh[nd]);
                mma_bf16(O[nd], Pha, vl[nd]);
                mma_bf16(O[nd], Pla, vh[nd]);
            }
        }
        __syncthreads();   // done reading smem before next tile overwrites
    }

    // ---- finalize + write bf16 planes ----
    float i0 = 1.f / l0, i1 = 1.f / l1;
    int r0 = q0 + w * 16 + (lane >> 2);
    size_t row0 = (size_t)(b * SS + r0) * DD + h * 64;
    size_t row1 = row0 + 8 * DD;
#pragma unroll
    for (int nd = 0; nd < 8; nd++) {
        int col = nd * 8 + (lane & 3) * 2;
        uint32_t hi, lo;
        split2(O[nd][0] * i0, O[nd][1] * i0, hi, lo);
        *(uint32_t*)(ohi + row0 + col) = hi;
        *(uint32_t*)(olo + row0 + col) = lo;
        split2(O[nd][2] * i1, O[nd][3] * i1, hi, lo);
        *(uint32_t*)(ohi + row1 + col) = hi;
        *(uint32_t*)(olo + row1 + col) = lo;
    }
}

// ---------------- MoE router ----------------
__global__ void router_kernel(const float* __restrict__ h2, const float* __restrict__ Wg,
                              float* __restrict__ probs, float* __restrict__ topw,
                              int* __restrict__ topi, int* __restrict__ slot_tok,
                              int* __restrict__ tok_slot, int* __restrict__ cnt) {
    int t = blockIdx.x, tid = threadIdx.x;  // 128 threads
    const float* hr = h2 + (size_t)t * DD;
    float a0 = 0, a1 = 0, a2 = 0, a3 = 0;
    for (int d = tid; d < DD; d += 128) {
        float hv = hr[d];
        a0 += hv * Wg[d];
        a1 += hv * Wg[DD + d];
        a2 += hv * Wg[2 * DD + d];
        a3 += hv * Wg[3 * DD + d];
    }
    __shared__ float r[4][128];
    r[0][tid] = a0; r[1][tid] = a1; r[2][tid] = a2; r[3][tid] = a3;
    __syncthreads();
    for (int o = 64; o > 0; o >>= 1) {
        if (tid < o) {
#pragma unroll
            for (int e = 0; e < 4; e++) r[e][tid] += r[e][tid + o];
        }
        __syncthreads();
    }
    if (tid == 0) {
        float l[4] = {r[0][0], r[1][0], r[2][0], r[3][0]};
        float m = fmaxf(fmaxf(l[0], l[1]), fmaxf(l[2], l[3]));
        float p[4], sum = 0.f;
#pragma unroll
        for (int e = 0; e < 4; e++) { p[e] = __expf(l[e] - m); sum += p[e]; }
#pragma unroll
        for (int e = 0; e < 4; e++) { p[e] /= sum; probs[t * 4 + e] = p[e]; }
        int i0 = 0;
#pragma unroll
        for (int e = 1; e < 4; e++) if (p[e] > p[i0]) i0 = e;
        int i1 = -1;
#pragma unroll
        for (int e = 0; e < 4; e++)
            if (e != i0 && (i1 < 0 || p[e] > p[i1])) i1 = e;
        float w0 = p[i0], w1 = p[i1], ws = w0 + w1;
        w0 /= ws; w1 /= ws;
        int pos0 = atomicAdd(&cnt[i0], 1);
        slot_tok[i0 * TT + pos0] = t;
        tok_slot[t * 2]     = i0 * TT + pos0;
        int pos1 = atomicAdd(&cnt[i1], 1);
        slot_tok[i1 * TT + pos1] = t;
        tok_slot[t * 2 + 1] = i1 * TT + pos1;
        topw[t * 2] = w0; topw[t * 2 + 1] = w1;
        topi[t * 2] = i0; topi[t * 2 + 1] = i1;
    }
}

// ---------------- aux loss ----------------
__global__ void aux_kernel(const float* __restrict__ probs, const int* __restrict__ topi,
                           float* __restrict__ auxout) {
    int tid = threadIdx.x;  // 512
    float ps[4] = {0, 0, 0, 0};
    float cs[4] = {0, 0, 0, 0};
    for (int t = tid; t < TT; t += 512) {
#pragma unroll
        for (int e = 0; e < 4; e++) ps[e] += probs[t * 4 + e];
        cs[topi[t * 2]] += 1.f;
        cs[topi[t * 2 + 1]] += 1.f;
    }
    __shared__ float sp[4][512], sc[4][512];
#pragma unroll
    for (int e = 0; e < 4; e++) { sp[e][tid] = ps[e]; sc[e][tid] = cs[e]; }
    __syncthreads();
    for (int o = 256; o > 0; o >>= 1) {
        if (tid < o) {
#pragma unroll
            for (int e = 0; e < 4; e++) {
                sp[e][tid] += sp[e][tid + o];
                sc[e][tid] += sc[e][tid + o];
            }
        }
        __syncthreads();
    }
    if (tid == 0) {
        float aux = 0.f;
#pragma unroll
        for (int e = 0; e < 4; e++) {
            float fi = sc[e][0] / (float)(TT * KSEL);
            float Pi = sp[e][0] / (float)TT;
            aux += fi * Pi;
        }
        auxout[0] = 0.01f * (float)EE * aux;
    }
}

// ---------------- final combine (scalar stores) ----------------
__global__ void combine_kernel(const float* __restrict__ x1, const float* __restrict__ sdown,
                               const float* __restrict__ eo, const float* __restrict__ topw,
                               const int* __restrict__ tok_slot, float* __restrict__ xout) {
    int t = blockIdx.x, tid = threadIdx.x;
    int c = tid * 4;
    int s0 = tok_slot[t * 2], s1 = tok_slot[t * 2 + 1];
    float w0 = topw[t * 2], w1 = topw[t * 2 + 1];
    float4 a  = *(const float4*)(x1 + (size_t)t * DD + c);
    float4 sd = *(const float4*)(sdown + (size_t)t * DD + c);
    float4 e0 = *(const float4*)(eo + (size_t)s0 * DD + c);
    float4 e1 = *(const float4*)(eo + (size_t)s1 * DD + c);
    float* o = xout + (size_t)t * DD + c;
    o[0] = a.x + sd.x + w0 * e0.x + w1 * e1.x;
    o[1] = a.y + sd.y + w0 * e0.y + w1 * e1.y;
    o[2] = a.z + sd.z + w0 * e0.z + w1 * e1.z;
    o[3] = a.w + sd.w + w0 * e0.w + w1 * e1.w;
}

// ---------------- launch ------------------------------------------------------
extern "C" void kernel_launch(void* const* d_in, const int* in_sizes, int n_in,
                              void* d_out, int out_size) {
    const float* x      = (const float*)d_in[0];
    const float* ln1_g  = (const float*)d_in[1];
    const float* ln1_b  = (const float*)d_in[2];
    const float* Wqkv   = (const float*)d_in[3];
    const float* bqkv   = (const float*)d_in[4];
    const float* Wo     = (const float*)d_in[5];
    const float* bo     = (const float*)d_in[6];
    const float* ln2_g  = (const float*)d_in[7];
    const float* ln2_b  = (const float*)d_in[8];
    const float* Wg     = (const float*)d_in[9];
    const float* We_up  = (const float*)d_in[10];
    const float* be_up  = (const float*)d_in[11];
    const float* We_dn  = (const float*)d_in[12];
    const float* be_dn  = (const float*)d_in[13];
    const float* Ws_up  = (const float*)d_in[14];
    const float* bs_up  = (const float*)d_in[15];
    const float* Ws_dn  = (const float*)d_in[16];
    const float* bs_dn  = (const float*)d_in[17];

    float* F = nullptr; int* I = nullptr;
    __nv_bfloat16* BH = nullptr; __nv_bfloat16* BL = nullptr;
    cudaGetSymbolAddress((void**)&F, g_f);
    cudaGetSymbolAddress((void**)&I, g_i);
    cudaGetSymbolAddress((void**)&BH, g_bh);
    cudaGetSymbolAddress((void**)&BL, g_bl);

    static bool attr_done = false;
    if (!attr_done) {
        cudaFuncSetAttribute(hgemm_nt<0>, cudaFuncAttributeMaxDynamicSharedMemorySize, SMEM_GEMM);
        cudaFuncSetAttribute(hgemm_nt<1>, cudaFuncAttributeMaxDynamicSharedMemorySize, SMEM_GEMM);
        cudaFuncSetAttribute(hgemm_nt<2>, cudaFuncAttributeMaxDynamicSharedMemorySize, SMEM_GEMM);
        cudaFuncSetAttribute(hgemm_nt<3>, cudaFuncAttributeMaxDynamicSharedMemorySize, SMEM_GEMM);
        attr_done = true;
    }

    float* x1    = F + OFF_X1;
    float* h2f   = F + OFF_H2F;
    float* sdown = F + OFF_SDOWN;
    float* eob   = F + OFF_EO;
    float* probs = F + OFF_PROBS;
    float* topw  = F + OFF_TOPW;
    int* slot_tok = I + IOFF_SLOT;
    int* tok_slot = I + IOFF_TOKSLOT;
    int* topi     = I + IOFF_TOPI;
    int* cnt      = I + IOFF_CNT;

    float* outp = (float*)d_out;
    float* auxp = nullptr;
    float* xout = outp;
    if (out_size == TT * DD + 1) { auxp = outp; xout = outp + 1; }

    cudaMemsetAsync(cnt, 0, EE * sizeof(int));

    // 0) ALL weight conversions in one fused kernel
    {
        ConvSrcs cs;
        cs.p[0] = Wqkv; cs.p[1] = Wo; cs.p[2] = We_up;
        cs.p[3] = We_dn; cs.p[4] = Ws_up; cs.p[5] = Ws_dn;
        int nblk = (int)((CONV_TOTAL / 4 + 255) / 256);
        conv_all_kernel<<<nblk, 256>>>(cs, BH, BL);
    }

    // 1) LN1 -> bf16 planes
    ln_kernel<0><<<TT, 256>>>(x, ln1_g, ln1_b, nullptr, BH + BO_H, BL + BO_H);
    // 2) QKV projection -> bf16 planes (EPI=3)
    hgemm_nt<3><<<dim3(24, 32, 1), 128, SMEM_GEMM>>>(
        BH + BO_H, BL + BO_H, BH + BO_WQKV, BL + BO_WQKV, bqkv, nullptr,
        nullptr, BH + BO_QKV, BL + BO_QKV, TT, 3 * DD, DD, nullptr, nullptr, 0, 0, 0, 0, 0);
    // 3) tensor-core causal attention -> bf16 planes
    attn_mma_kernel<<<dim3(SS / 64, Bb * HH), 128>>>(
        BH + BO_QKV, BL + BO_QKV, BH + BO_ATTN, BL + BO_ATTN);
    // 4) output proj + residual -> x1 fp32
    hgemm_nt<2><<<dim3(8, 32, 1), 128, SMEM_GEMM>>>(
        BH + BO_ATTN, BL + BO_ATTN, BH + BO_WO, BL + BO_WO, bo, x,
        x1, nullptr, nullptr, TT, DD, DD, nullptr, nullptr, 0, 0, 0, 0, 0);
    // 5) LN2 -> fp32 + bf16 planes
    ln_kernel<1><<<TT, 256>>>(x1, ln2_g, ln2_b, h2f, BH + BO_H2, BL + BO_H2);
    // 6) router
    router_kernel<<<TT, 128>>>(h2f, Wg, probs, topw, topi, slot_tok, tok_slot, cnt);
    // 7) aux loss
    if (auxp) aux_kernel<<<1, 512>>>(probs, topi, auxp);
    // 8) expert up (gathered, gelu -> bf16 planes)
    hgemm_nt<1><<<dim3(32, 32, 4), 128, SMEM_GEMM>>>(
        BH + BO_H2, BL + BO_H2, BH + BO_WEUP, BL + BO_WEUP, be_up, nullptr,
        nullptr, BH + BO_UPB, BL + BO_UPB, TT, HIDD, DD, slot_tok, cnt,
        0, (size_t)HIDD * DD, (size_t)HIDD, (size_t)TT * HIDD, (size_t)TT);
    // 9) expert down -> eob fp32
    hgemm_nt<0><<<dim3(8, 32, 4), 128, SMEM_GEMM>>>(
        BH + BO_UPB, BL + BO_UPB, BH + BO_WEDN, BL + BO_WEDN, be_dn, nullptr,
        eob, nullptr, nullptr, TT, DD, HIDD, nullptr, cnt,
        (size_t)TT * HIDD, (size_t)DD * HIDD, (size_t)DD, (size_t)TT * DD, 0);
    // 10) shared expert up (gelu -> bf16 planes)
    hgemm_nt<1><<<dim3(32, 32, 1), 128, SMEM_GEMM>>>(
        BH + BO_H2, BL + BO_H2, BH + BO_WSUP, BL + BO_WSUP, bs_up, nullptr,
        nullptr, BH + BO_SUP, BL + BO_SUP, TT, HIDD, DD, nullptr, nullptr, 0, 0, 0, 0, 0);
    // 11) shared expert down -> sdown fp32
    hgemm_nt<0><<<dim3(8, 32, 1), 128, SMEM_GEMM>>>(
        BH + BO_SUP, BL + BO_SUP, BH + BO_WSDN, BL + BO_WSDN, bs_dn, nullptr,
        sdown, nullptr, nullptr, TT, DD, HIDD, nullptr, nullptr, 0, 0, 0, 0, 0);
    // 12) combine
    combine_kernel<<<TT, 256>>>(x1, sdown, eob, topw, tok_slot, xout);
}

// round 17
// speedup vs baseline: 2.7171x; 1.0600x over previous
#include <cuda_runtime.h>
#include <cuda_bf16.h>
#include <math.h>
#include <stdint.h>

// ---------------- problem constants ----------------
#define Bb   2
#define SS   2048
#define DD   1024
#define HH   16
#define HDIM 64
#define EE   4
#define KSEL 2
#define HIDD 4096
#define TT   (Bb*SS)   // 4096 tokens

// ---------------- fp32 scratch ----------------
static const size_t OFF_X1    = 0;                                   // TT*DD
static const size_t OFF_H2F   = OFF_X1    + (size_t)TT*DD;           // TT*DD
static const size_t OFF_SDOWN = OFF_H2F   + (size_t)TT*DD;           // TT*DD
static const size_t OFF_EO    = OFF_SDOWN + (size_t)TT*DD;           // EE*TT*DD
static const size_t OFF_PROBS = OFF_EO    + (size_t)EE*TT*DD;        // TT*EE
static const size_t OFF_TOPW  = OFF_PROBS + (size_t)TT*EE;           // TT*KSEL
static const size_t F_TOTAL   = OFF_TOPW  + (size_t)TT*KSEL;
__device__ float g_f[F_TOTAL];

// ---------------- bf16 hi/lo planes (weights contiguous & in conv order) ------
static const size_t BO_WQKV = 0;                                 // 3*DD*DD
static const size_t BO_WO   = BO_WQKV + (size_t)3*DD*DD;         // DD*DD
static const size_t BO_WEUP = BO_WO   + (size_t)DD*DD;           // EE*HIDD*DD
static const size_t BO_WEDN = BO_WEUP + (size_t)EE*HIDD*DD;      // EE*DD*HIDD
static const size_t BO_WSUP = BO_WEDN + (size_t)EE*DD*HIDD;      // HIDD*DD
static const size_t BO_WSDN = BO_WSUP + (size_t)HIDD*DD;         // DD*HIDD
static const size_t BO_H    = BO_WSDN + (size_t)DD*HIDD;         // TT*DD
static const size_t BO_ATTN = BO_H    + (size_t)TT*DD;           // TT*DD
static const size_t BO_H2   = BO_ATTN + (size_t)TT*DD;           // TT*DD
static const size_t BO_SUP  = BO_H2   + (size_t)TT*DD;           // TT*HIDD
static const size_t BO_UPB  = BO_SUP  + (size_t)TT*HIDD;         // EE*TT*HIDD
static const size_t BO_QKV  = BO_UPB  + (size_t)EE*TT*HIDD;      // TT*3*DD
static const size_t B_TOTAL = BO_QKV  + (size_t)TT*3*DD;
__device__ __nv_bfloat16 g_bh[B_TOTAL];
__device__ __nv_bfloat16 g_bl[B_TOTAL];

static const size_t CONV_TOTAL = BO_H;   // weights only

// ---------------- int scratch ----------------
static const size_t IOFF_SLOT    = 0;                       // EE*TT
static const size_t IOFF_TOKSLOT = IOFF_SLOT + EE*TT;       // TT*KSEL
static const size_t IOFF_TOPI    = IOFF_TOKSLOT + TT*KSEL;  // TT*KSEL
static const size_t IOFF_CNT     = IOFF_TOPI + TT*KSEL;     // EE
__device__ int g_i[IOFF_CNT + EE];

// ---------------- helpers ----------------
__device__ __forceinline__ float gelu_tanh(float x) {
    float z = 0.7978845608028654f * (x + 0.044715f * x * x * x);
    float e = __expf(2.f * z);
    float th = 1.f - 2.f / (e + 1.f);
    return 0.5f * x * (1.f + th);
}

__device__ __forceinline__ void mma_bf16(float* d, const uint32_t* a, const uint32_t* b) {
    asm volatile(
        "mma.sync.aligned.m16n8k16.row.col.f32.bf16.bf16.f32 "
        "{%0,%1,%2,%3}, {%4,%5,%6,%7}, {%8,%9}, {%0,%1,%2,%3};\n"
        : "+f"(d[0]), "+f"(d[1]), "+f"(d[2]), "+f"(d[3])
        : "r"(a[0]), "r"(a[1]), "r"(a[2]), "r"(a[3]), "r"(b[0]), "r"(b[1]));
}

__device__ __forceinline__ void ldsm4(uint32_t* r, uint32_t addr) {
    asm volatile("ldmatrix.sync.aligned.m8n8.x4.shared.b16 {%0,%1,%2,%3}, [%4];"
                 : "=r"(r[0]), "=r"(r[1]), "=r"(r[2]), "=r"(r[3]) : "r"(addr));
}

__device__ __forceinline__ void ldsm4t(uint32_t* r, uint32_t addr) {
    asm volatile("ldmatrix.sync.aligned.m8n8.x4.trans.shared.b16 {%0,%1,%2,%3}, [%4];"
                 : "=r"(r[0]), "=r"(r[1]), "=r"(r[2]), "=r"(r[3]) : "r"(addr));
}

__device__ __forceinline__ void split2(float x, float y, uint32_t& hi, uint32_t& lo) {
    __nv_bfloat16 hx = __float2bfloat16_rn(x);
    __nv_bfloat16 hy = __float2bfloat16_rn(y);
    __nv_bfloat16 lx = __float2bfloat16_rn(x - __bfloat162float(hx));
    __nv_bfloat16 ly = __float2bfloat16_rn(y - __bfloat162float(hy));
    __nv_bfloat162 h2 = __nv_bfloat162(hx, hy);
    __nv_bfloat162 l2 = __nv_bfloat162(lx, ly);
    hi = *reinterpret_cast<uint32_t*>(&h2);
    lo = *reinterpret_cast<uint32_t*>(&l2);
}

__device__ __forceinline__ void cpa16(uint32_t dst, const void* src, int srcbytes) {
    asm volatile("cp.async.cg.shared.global [%0], [%1], 16, %2;"
                 :: "r"(dst), "l"(src), "r"(srcbytes));
}
__device__ __forceinline__ void cpa_commit() { asm volatile("cp.async.commit_group;"); }
__device__ __forceinline__ void cpa_wait_all() { asm volatile("cp.async.wait_group 0;"); }
__device__ __forceinline__ void cpa_wait_1()   { asm volatile("cp.async.wait_group 1;"); }

// ---------------- fused fp32 -> bf16 hi/lo convert for ALL weights ------------
struct ConvSrcs { const float* p[6]; };
__global__ void conv_all_kernel(ConvSrcs srcs, __nv_bfloat16* __restrict__ hi,
                                __nv_bfloat16* __restrict__ lo) {
    size_t i = ((size_t)blockIdx.x * blockDim.x + threadIdx.x) * 4;
    if (i >= CONV_TOTAL) return;
    const size_t pf0 = 0;
    const size_t pf1 = (size_t)3 * DD * DD;
    const size_t pf2 = pf1 + (size_t)DD * DD;
    const size_t pf3 = pf2 + (size_t)EE * HIDD * DD;
    const size_t pf4 = pf3 + (size_t)EE * DD * HIDD;
    const size_t pf5 = pf4 + (size_t)HIDD * DD;
    int s; size_t base;
    if      (i < pf1) { s = 0; base = pf0; }
    else if (i < pf2) { s = 1; base = pf1; }
    else if (i < pf3) { s = 2; base = pf2; }
    else if (i < pf4) { s = 3; base = pf3; }
    else if (i < pf5) { s = 4; base = pf4; }
    else              { s = 5; base = pf5; }
    float4 v = *(const float4*)(srcs.p[s] + (i - base));
    uint32_t h0, l0, h1, l1;
    split2(v.x, v.y, h0, l0);
    split2(v.z, v.w, h1, l1);
    *(uint32_t*)(hi + i)     = h0;
    *(uint32_t*)(hi + i + 2) = h1;
    *(uint32_t*)(lo + i)     = l0;
    *(uint32_t*)(lo + i + 2) = l1;
}

// ---------------- LayerNorm ----------------
template <int MODE>
__global__ void ln_kernel(const float* __restrict__ x, const float* __restrict__ g,
                          const float* __restrict__ b, float* __restrict__ outf,
                          __nv_bfloat16* __restrict__ ohi, __nv_bfloat16* __restrict__ olo) {
    int t = blockIdx.x, tid = threadIdx.x;
    const float* xr = x + (size_t)t * DD;
    float v[4], s = 0.f, sq = 0.f;
#pragma unroll
    for (int k = 0; k < 4; k++) {
        v[k] = xr[tid + k * 256];
        s += v[k]; sq += v[k] * v[k];
    }
    __shared__ float rs[256], rq[256];
    rs[tid] = s; rq[tid] = sq;
    __syncthreads();
    for (int o = 128; o > 0; o >>= 1) {
        if (tid < o) { rs[tid] += rs[tid + o]; rq[tid] += rq[tid + o]; }
        __syncthreads();
    }
    float mean = rs[0] * (1.f / DD);
    float var  = rq[0] * (1.f / DD) - mean * mean;
    float inv  = rsqrtf(var + 1e-5f);
#pragma unroll
    for (int k = 0; k < 4; k++) {
        int d = tid + k * 256;
        float val = (v[k] - mean) * inv * g[d] + b[d];
        if (MODE == 1) outf[(size_t)t * DD + d] = val;
        __nv_bfloat16 hx = __float2bfloat16_rn(val);
        __nv_bfloat16 lx = __float2bfloat16_rn(val - __bfloat162float(hx));
        ohi[(size_t)t * DD + d] = hx;
        olo[(size_t)t * DD + d] = lx;
    }
}

// ---------------- tensor-core NT GEMM, split-bf16 planes ----------------------
// EPI: 0 fp32; 1 gelu->bf16 planes; 2 fp32+resid; 3 bf16 planes (no act)
#define LDAH 40            // smem row pitch in halves
#define ARR_B   10240      // one plane: 128 rows * 80B
#define STAGE_B 40960      // 4 planes
#define SMEM_GEMM 81920    // 2 stages
template <int EPI>
__global__ void __launch_bounds__(128) hgemm_nt(
    const __nv_bfloat16* __restrict__ Ahi, const __nv_bfloat16* __restrict__ Alo,
    const __nv_bfloat16* __restrict__ Bhi, const __nv_bfloat16* __restrict__ Blo,
    const float* __restrict__ bias, const float* __restrict__ resid,
    float* __restrict__ Cf, __nv_bfloat16* __restrict__ Chi, __nv_bfloat16* __restrict__ Clo,
    int M, int N, int Kd,
    const int* __restrict__ rowIdx, const int* __restrict__ cnt,
    size_t aZ, size_t bZ, size_t biasZ, size_t cZ, size_t idxZ) {
    int z = blockIdx.z;
    Ahi += (size_t)z * aZ; Alo += (size_t)z * aZ;
    Bhi += (size_t)z * bZ; Blo += (size_t)z * bZ;
    bias += (size_t)z * biasZ;
    if (EPI == 1 || EPI == 3) { Chi += (size_t)z * cZ; Clo += (size_t)z * cZ; }
    else                      { Cf  += (size_t)z * cZ; }
    if (rowIdx) rowIdx += (size_t)z * idxZ;
    if (cnt) M = cnt[z];
    int mBase = blockIdx.y * 128;
    if (mBase >= M) return;
    int n0 = blockIdx.x * 128;

    extern __shared__ __align__(16) uint16_t smem_dyn[];
    uint32_t smemBase = (uint32_t)__cvta_generic_to_shared(smem_dyn);

    int tid = threadIdx.x;
    int wid = tid >> 5, lane = tid & 31;
    int warp_m = (wid & 1) * 64;
    int warp_n = (wid >> 1) * 64;

    ptrdiff_t dAlo = Alo - Ahi;
    ptrdiff_t dBlo = Blo - Bhi;
    int rowB0 = tid >> 2;
    int kh0   = (tid & 3) * 8;
    const __nv_bfloat16* aHiP[4];
    int aOK[4];
    uint32_t sOff[4];
#pragma unroll
    for (int i = 0; i < 4; i++) {
        int row = rowB0 + 32 * i;
        sOff[i] = (uint32_t)(row * LDAH + kh0) * 2;
        int gmr = mBase + row;
        bool ok = gmr < M;
        int sr = ok ? (rowIdx ? rowIdx[gmr] : gmr) : 0;
        aHiP[i] = Ahi + (size_t)sr * Kd + kh0;
        aOK[i] = ok ? 16 : 0;
    }
    const __nv_bfloat16* bHi0 = Bhi + (size_t)(n0 + rowB0) * Kd + kh0;

    uint32_t aOff[4];
#pragma unroll
    for (int mt = 0; mt < 4; mt++) {
        int row = warp_m + mt * 16 + (lane & 15);
        int colh = (lane >> 4) * 8;
        aOff[mt] = (uint32_t)(row * LDAH + colh) * 2;
    }
    uint32_t bOff[4];
#pragma unroll
    for (int np = 0; np < 4; np++) {
        int row = warp_n + np * 16 + (lane & 7) + ((lane >> 4) << 3);
        int colh = ((lane >> 3) & 1) * 8;
        bOff[np] = (uint32_t)(row * LDAH + colh) * 2;
    }

    float c[4][8][4];
#pragma unroll
    for (int i = 0; i < 4; i++)
#pragma unroll
        for (int j = 0; j < 8; j++)
#pragma unroll
            for (int k = 0; k < 4; k++) c[i][j][k] = 0.f;

    int nK = Kd >> 5;

    {
        uint32_t sb = smemBase;
#pragma unroll
        for (int i = 0; i < 4; i++) {
            const __nv_bfloat16* bp = bHi0 + (size_t)(32 * i) * Kd;
            cpa16(sb + sOff[i],             aHiP[i], aOK[i]);
            cpa16(sb + ARR_B + sOff[i],     aHiP[i] + dAlo, aOK[i]);
            cpa16(sb + 2 * ARR_B + sOff[i], bp, 16);
            cpa16(sb + 3 * ARR_B + sOff[i], bp + dBlo, 16);
        }
        cpa_commit();
    }

    for (int kt = 0; kt < nK; kt++) {
        int cur = kt & 1;
        cpa_wait_all();
        __syncthreads();
        if (kt + 1 < nK) {
            uint32_t sb = smemBase + (cur ^ 1) * STAGE_B;
            int koff = (kt + 1) * 32;
#pragma unroll
            for (int i = 0; i < 4; i++) {
                const __nv_bfloat16* bp = bHi0 + (size_t)(32 * i) * Kd + koff;
                cpa16(sb + sOff[i],             aHiP[i] + koff, aOK[i]);
                cpa16(sb + ARR_B + sOff[i],     aHiP[i] + dAlo + koff, aOK[i]);
                cpa16(sb + 2 * ARR_B + sOff[i], bp, 16);
                cpa16(sb + 3 * ARR_B + sOff[i], bp + dBlo, 16);
            }
            cpa_commit();
        }
        uint32_t stageB = smemBase + cur * STAGE_B;
#pragma unroll
        for (int ks = 0; ks < 2; ks++) {
            uint32_t kb = ks * 32;
            uint32_t ah[4][4], al[4][4], bh[8][2], bl[8][2];
#pragma unroll
            for (int mt = 0; mt < 4; mt++) {
                ldsm4(ah[mt], stageB + aOff[mt] + kb);
                ldsm4(al[mt], stageB + ARR_B + aOff[mt] + kb);
            }
#pragma unroll
            for (int np = 0; np < 4; np++) {
                uint32_t r[4];
                ldsm4(r, stageB + 2 * ARR_B + bOff[np] + kb);
                bh[2 * np][0] = r[0]; bh[2 * np][1] = r[1];
                bh[2 * np + 1][0] = r[2]; bh[2 * np + 1][1] = r[3];
                ldsm4(r, stageB + 3 * ARR_B + bOff[np] + kb);
                bl[2 * np][0] = r[0]; bl[2 * np][1] = r[1];
                bl[2 * np + 1][0] = r[2]; bl[2 * np + 1][1] = r[3];
            }
#pragma unroll
            for (int mt = 0; mt < 4; mt++)
#pragma unroll
                for (int nt = 0; nt < 8; nt++) {
                    mma_bf16(c[mt][nt], ah[mt], bh[nt]);
                    mma_bf16(c[mt][nt], ah[mt], bl[nt]);
                    mma_bf16(c[mt][nt], al[mt], bh[nt]);
                }
        }
    }

#pragma unroll
    for (int mt = 0; mt < 4; mt++) {
#pragma unroll
        for (int nt = 0; nt < 8; nt++) {
            int col = n0 + warp_n + nt * 8 + (lane & 3) * 2;
            float2 bb = *(const float2*)(bias + col);
#pragma unroll
            for (int half = 0; half < 2; half++) {
                int r = mBase + warp_m + mt * 16 + (lane >> 2) + half * 8;
                if (r >= M) continue;
                float v0 = c[mt][nt][half * 2 + 0] + bb.x;
                float v1 = c[mt][nt][half * 2 + 1] + bb.y;
                if (EPI == 1 || EPI == 3) {
                    if (EPI == 1) { v0 = gelu_tanh(v0); v1 = gelu_tanh(v1); }
                    uint32_t hi, lo;
                    split2(v0, v1, hi, lo);
                    *(uint32_t*)(Chi + (size_t)r * N + col) = hi;
                    *(uint32_t*)(Clo + (size_t)r * N + col) = lo;
                } else {
                    if (EPI == 2) {
                        float2 rr = *(const float2*)(resid + (size_t)r * N + col);
                        v0 += rr.x; v1 += rr.y;
                    }
                    *(float2*)(Cf + (size_t)r * N + col) = make_float2(v0, v1);
                }
            }
        }
    }
}

// ---------------- tensor-core causal flash attention --------------------------
// CTA: 64 queries of one (b,h); 4 warps x 16 queries; key tiles of 64.
// K and V both row-major in smem (cp.async); V fragments via ldmatrix.trans.
// 2-stage double buffer.
#define APITCH 72                 // smem row pitch in halves (144B rows, 16B aligned)
#define AARR   (64 * APITCH * 2)  // 9216 bytes per plane
#define ASTAGE (4 * AARR)         // 36864 bytes per stage (Khi,Klo,Vhi,Vlo)
#define ATTN_SMEM (2 * ASTAGE)    // 73728
__global__ void __launch_bounds__(128) attn_mma_kernel(
    const __nv_bfloat16* __restrict__ qh, const __nv_bfloat16* __restrict__ ql,
    __nv_bfloat16* __restrict__ ohi, __nv_bfloat16* __restrict__ olo) {
    extern __shared__ __align__(16) uint16_t smA[];
    uint32_t smBase = (uint32_t)__cvta_generic_to_shared(smA);

    int qblk = gridDim.x - 1 - blockIdx.x;   // heavy CTAs first
    int q0 = qblk * 64;
    int bh = blockIdx.y;
    int b = bh >> 4, h = bh & 15;
    int tid = threadIdx.x;
    int w = tid >> 5, lane = tid & 31;
    ptrdiff_t dlo = ql - qh;

    // ---- ldmatrix offsets ----
    uint32_t aOff[4];   // Q A-frags
#pragma unroll
    for (int kk = 0; kk < 4; kk++) {
        int row = w * 16 + (lane & 15);
        int colh = (lane >> 4) * 8 + kk * 16;
        aOff[kk] = (uint32_t)(row * APITCH + colh) * 2;
    }
    uint32_t bOff[4];   // K B-frags (non-trans)
#pragma unroll
    for (int np = 0; np < 4; np++) {
        int row = np * 16 + (lane & 7) + ((lane >> 4) << 3);
        int colh = ((lane >> 3) & 1) * 8;
        bOff[np] = (uint32_t)(row * APITCH + colh) * 2;
    }
    uint32_t vOff[4];   // V B-frags via ldmatrix.trans: row=key, col=dim
#pragma unroll
    for (int np = 0; np < 4; np++) {
        int rowk = lane & 15;                        // key within 16-chunk
        int dim  = np * 16 + ((lane >> 4) << 3);     // output dim base
        vOff[np] = (uint32_t)(rowk * APITCH + dim) * 2;
    }

    // ---- stage Q into stage0 K area, load A-frags ----
    const __nv_bfloat16* qbase = qh + (size_t)(b * SS + q0) * (3 * DD) + h * 64;
#pragma unroll
    for (int i = 0; i < 4; i++) {
        int seg = tid + i * 128;
        int row = seg >> 3, c8 = (seg & 7) * 8;
        const __nv_bfloat16* src = qbase + (size_t)row * (3 * DD) + c8;
        uint32_t doff = (uint32_t)(row * APITCH + c8) * 2;
        cpa16(smBase + doff, src, 16);
        cpa16(smBase + AARR + doff, src + dlo, 16);
    }
    cpa_commit();
    cpa_wait_all();
    __syncthreads();
    uint32_t Qh[4][4], Ql[4][4];
#pragma unroll
    for (int kk = 0; kk < 4; kk++) {
        ldsm4(Qh[kk], smBase + aOff[kk]);
        ldsm4(Ql[kk], smBase + AARR + aOff[kk]);
    }
    __syncthreads();

    float O[8][4];
#pragma unroll
    for (int i = 0; i < 8; i++)
#pragma unroll
        for (int j = 0; j < 4; j++) O[i][j] = 0.f;
    float m0 = -1e30f, m1 = -1e30f, l0 = 0.f, l1 = 0.f;

    int ntile = qblk + 1;
    const __nv_bfloat16* kvbase = qh + (size_t)(b * SS) * (3 * DD) + h * 64;

    // prefetch tile 0 into stage 0 (K + V, hi + lo)
    {
        uint32_t sb = smBase;
#pragma unroll
        for (int i = 0; i < 4; i++) {
            int seg = tid + i * 128;
            int row = seg >> 3, c8 = (seg & 7) * 8;
            const __nv_bfloat16* kp = kvbase + (size_t)row * (3 * DD) + DD + c8;
            uint32_t doff = (uint32_t)(row * APITCH + c8) * 2;
            cpa16(sb + doff,            kp, 16);
            cpa16(sb + AARR + doff,     kp + dlo, 16);
            cpa16(sb + 2 * AARR + doff, kp + DD, 16);
            cpa16(sb + 3 * AARR + doff, kp + DD + dlo, 16);
        }
        cpa_commit();
    }

    for (int t = 0; t < ntile; t++) {
        int cur = t & 1;
        uint32_t base_cur = smBase + cur * ASTAGE;
        bool more = (t + 1 < ntile);
        if (more) {
            uint32_t sb = smBase + (cur ^ 1) * ASTAGE;
            int t0n = (t + 1) * 64;
#pragma unroll
            for (int i = 0; i < 4; i++) {
                int seg = tid + i * 128;
                int row = seg >> 3, c8 = (seg & 7) * 8;
                const __nv_bfloat16* kp = kvbase + (size_t)(t0n + row) * (3 * DD) + DD + c8;
                uint32_t doff = (uint32_t)(row * APITCH + c8) * 2;
                cpa16(sb + doff,            kp, 16);
                cpa16(sb + AARR + doff,     kp + dlo, 16);
                cpa16(sb + 2 * AARR + doff, kp + DD, 16);
                cpa16(sb + 3 * AARR + doff, kp + DD + dlo, 16);
            }
            cpa_commit();
        }
        if (more) cpa_wait_1(); else cpa_wait_all();
        __syncthreads();

        int t0 = t * 64;
        // ---- scores S[16q x 64key] ----
        float s[8][4];
#pragma unroll
        for (int i = 0; i < 8; i++)
#pragma unroll
            for (int j = 0; j < 4; j++) s[i][j] = 0.f;
#pragma unroll
        for (int ks = 0; ks < 4; ks++) {
            uint32_t kb = ks * 32;
            uint32_t bhf[8][2], blf[8][2];
#pragma unroll
            for (int np = 0; np < 4; np++) {
                uint32_t r[4];
                ldsm4(r, base_cur + bOff[np] + kb);
                bhf[2 * np][0] = r[0]; bhf[2 * np][1] = r[1];
                bhf[2 * np + 1][0] = r[2]; bhf[2 * np + 1][1] = r[3];
                ldsm4(r, base_cur + AARR + bOff[np] + kb);
                blf[2 * np][0] = r[0]; blf[2 * np][1] = r[1];
                blf[2 * np + 1][0] = r[2]; blf[2 * np + 1][1] = r[3];
            }
#pragma unroll
            for (int nt = 0; nt < 8; nt++) {
                mma_bf16(s[nt], Qh[ks], bhf[nt]);
                mma_bf16(s[nt], Qh[ks], blf[nt]);
                mma_bf16(s[nt], Ql[ks], bhf[nt]);
            }
        }
        // scale + causal mask (diagonal tile only)
#pragma unroll
        for (int nt = 0; nt < 8; nt++)
#pragma unroll
            for (int e = 0; e < 4; e++) s[nt][e] *= 0.125f;
        if (t0 == q0) {
            int kc = (lane & 3) * 2;
            int qr = w * 16 + (lane >> 2);
#pragma unroll
            for (int nt = 0; nt < 8; nt++) {
                int keyb = nt * 8 + kc;
                if (keyb     > qr)     s[nt][0] = -1e30f;
                if (keyb + 1 > qr)     s[nt][1] = -1e30f;
                if (keyb     > qr + 8) s[nt][2] = -1e30f;
                if (keyb + 1 > qr + 8) s[nt][3] = -1e30f;
            }
        }
        // ---- online softmax ----
        float mt0 = -1e30f, mt1 = -1e30f;
#pragma unroll
        for (int nt = 0; nt < 8; nt++) {
            mt0 = fmaxf(mt0, fmaxf(s[nt][0], s[nt][1]));
            mt1 = fmaxf(mt1, fmaxf(s[nt][2], s[nt][3]));
        }
        mt0 = fmaxf(mt0, __shfl_xor_sync(0xffffffffu, mt0, 1));
        mt0 = fmaxf(mt0, __shfl_xor_sync(0xffffffffu, mt0, 2));
        mt1 = fmaxf(mt1, __shfl_xor_sync(0xffffffffu, mt1, 1));
        mt1 = fmaxf(mt1, __shfl_xor_sync(0xffffffffu, mt1, 2));
        float mn0 = fmaxf(m0, mt0), mn1 = fmaxf(m1, mt1);
        float f0 = __expf(m0 - mn0), f1 = __expf(m1 - mn1);
        m0 = mn0; m1 = mn1;
        l0 *= f0; l1 *= f1;
#pragma unroll
        for (int nd = 0; nd < 8; nd++) {
            O[nd][0] *= f0; O[nd][1] *= f0;
            O[nd][2] *= f1; O[nd][3] *= f1;
        }
        float ls0 = 0.f, ls1 = 0.f;
#pragma unroll
        for (int nt = 0; nt < 8; nt++) {
            s[nt][0] = __expf(s[nt][0] - m0);
            s[nt][1] = __expf(s[nt][1] - m0);
            s[nt][2] = __expf(s[nt][2] - m1);
            s[nt][3] = __expf(s[nt][3] - m1);
            ls0 += s[nt][0] + s[nt][1];
            ls1 += s[nt][2] + s[nt][3];
        }
        ls0 += __shfl_xor_sync(0xffffffffu, ls0, 1);
        ls0 += __shfl_xor_sync(0xffffffffu, ls0, 2);
        ls1 += __shfl_xor_sync(0xffffffffu, ls1, 1);
        ls1 += __shfl_xor_sync(0xffffffffu, ls1, 2);
        l0 += ls0; l1 += ls1;

        // ---- PV: O += P @ V  (V frags via ldmatrix.trans on row-major V) ----
#pragma unroll
        for (int kk = 0; kk < 4; kk++) {
            uint32_t krow = (uint32_t)(kk * 16 * APITCH) * 2;  // advance 16 key rows
            uint32_t vh[8][2], vl[8][2];
#pragma unroll
            for (int np = 0; np < 4; np++) {
                uint32_t r[4];
                ldsm4t(r, base_cur + 2 * AARR + vOff[np] + krow);
                vh[2 * np][0] = r[0]; vh[2 * np][1] = r[1];
                vh[2 * np + 1][0] = r[2]; vh[2 * np + 1][1] = r[3];
                ldsm4t(r, base_cur + 3 * AARR + vOff[np] + krow);
                vl[2 * np][0] = r[0]; vl[2 * np][1] = r[1];
                vl[2 * np + 1][0] = r[2]; vl[2 * np + 1][1] = r[3];
            }
            uint32_t Pha[4], Pla[4];
            split2(s[2 * kk][0], s[2 * kk][1], Pha[0], Pla[0]);
            split2(s[2 * kk][2], s[2 * kk][3], Pha[1], Pla[1]);
            split2(s[2 * kk + 1][0], s[2 * kk + 1][1], Pha[2], Pla[2]);
            split2(s[2 * kk + 1][2], s[2 * kk + 1][3], Pha[3], Pla[3]);
#pragma unroll
            for (int nd = 0; nd < 8; nd++) {
                mma_bf16(O[nd], Pha, vh[nd]);
                mma_bf16(O[nd], Pha, vl[nd]);
                mma_bf16(O[nd], Pla, vh[nd]);
            }
        }
        __syncthreads();   // all reads of this stage done before its next overwrite
    }

    // ---- finalize + write bf16 planes ----
    float i0 = 1.f / l0, i1 = 1.f / l1;
    int r0 = q0 + w * 16 + (lane >> 2);
    size_t row0 = (size_t)(b * SS + r0) * DD + h * 64;
    size_t row1 = row0 + 8 * DD;
#pragma unroll
    for (int nd = 0; nd < 8; nd++) {
        int col = nd * 8 + (lane & 3) * 2;
        uint32_t hi, lo;
        split2(O[nd][0] * i0, O[nd][1] * i0, hi, lo);
        *(uint32_t*)(ohi + row0 + col) = hi;
        *(uint32_t*)(olo + row0 + col) = lo;
        split2(O[nd][2] * i1, O[nd][3] * i1, hi, lo);
        *(uint32_t*)(ohi + row1 + col) = hi;
        *(uint32_t*)(olo + row1 + col) = lo;
    }
}

// ---------------- MoE router ----------------
__global__ void router_kernel(const float* __restrict__ h2, const float* __restrict__ Wg,
                              float* __restrict__ probs, float* __restrict__ topw,
                              int* __restrict__ topi, int* __restrict__ slot_tok,
                              int* __restrict__ tok_slot, int* __restrict__ cnt) {
    int t = blockIdx.x, tid = threadIdx.x;  // 128 threads
    const float* hr = h2 + (size_t)t * DD;
    float a0 = 0, a1 = 0, a2 = 0, a3 = 0;
    for (int d = tid; d < DD; d += 128) {
        float hv = hr[d];
        a0 += hv * Wg[d];
        a1 += hv * Wg[DD + d];
        a2 += hv * Wg[2 * DD + d];
        a3 += hv * Wg[3 * DD + d];
    }
    __shared__ float r[4][128];
    r[0][tid] = a0; r[1][tid] = a1; r[2][tid] = a2; r[3][tid] = a3;
    __syncthreads();
    for (int o = 64; o > 0; o >>= 1) {
        if (tid < o) {
#pragma unroll
            for (int e = 0; e < 4; e++) r[e][tid] += r[e][tid + o];
        }
        __syncthreads();
    }
    if (tid == 0) {
        float l[4] = {r[0][0], r[1][0], r[2][0], r[3][0]};
        float m = fmaxf(fmaxf(l[0], l[1]), fmaxf(l[2], l[3]));
        float p[4], sum = 0.f;
#pragma unroll
        for (int e = 0; e < 4; e++) { p[e] = __expf(l[e] - m); sum += p[e]; }
#pragma unroll
        for (int e = 0; e < 4; e++) { p[e] /= sum; probs[t * 4 + e] = p[e]; }
        int i0 = 0;
#pragma unroll
        for (int e = 1; e < 4; e++) if (p[e] > p[i0]) i0 = e;
        int i1 = -1;
#pragma unroll
        for (int e = 0; e < 4; e++)
            if (e != i0 && (i1 < 0 || p[e] > p[i1])) i1 = e;
        float w0 = p[i0], w1 = p[i1], ws = w0 + w1;
        w0 /= ws; w1 /= ws;
        int pos0 = atomicAdd(&cnt[i0], 1);
        slot_tok[i0 * TT + pos0] = t;
        tok_slot[t * 2]     = i0 * TT + pos0;
        int pos1 = atomicAdd(&cnt[i1], 1);
        slot_tok[i1 * TT + pos1] = t;
        tok_slot[t * 2 + 1] = i1 * TT + pos1;
        topw[t * 2] = w0; topw[t * 2 + 1] = w1;
        topi[t * 2] = i0; topi[t * 2 + 1] = i1;
    }
}

// ---------------- aux loss ----------------
__global__ void aux_kernel(const float* __restrict__ probs, const int* __restrict__ topi,
                           float* __restrict__ auxout) {
    int tid = threadIdx.x;  // 512
    float ps[4] = {0, 0, 0, 0};
    float cs[4] = {0, 0, 0, 0};
    for (int t = tid; t < TT; t += 512) {
#pragma unroll
        for (int e = 0; e < 4; e++) ps[e] += probs[t * 4 + e];
        cs[topi[t * 2]] += 1.f;
        cs[topi[t * 2 + 1]] += 1.f;
    }
    __shared__ float sp[4][512], sc[4][512];
#pragma unroll
    for (int e = 0; e < 4; e++) { sp[e][tid] = ps[e]; sc[e][tid] = cs[e]; }
    __syncthreads();
    for (int o = 256; o > 0; o >>= 1) {
        if (tid < o) {
#pragma unroll
            for (int e = 0; e < 4; e++) {
                sp[e][tid] += sp[e][tid + o];
                sc[e][tid] += sc[e][tid + o];
            }
        }
        __syncthreads();
    }
    if (tid == 0) {
        float aux = 0.f;
#pragma unroll
        for (int e = 0; e < 4; e++) {
            float fi = sc[e][0] / (float)(TT * KSEL);
            float Pi = sp[e][0] / (float)TT;
            aux += fi * Pi;
        }
        auxout[0] = 0.01f * (float)EE * aux;
    }
}

// ---------------- final combine (scalar stores) ----------------
__global__ void combine_kernel(const float* __restrict__ x1, const float* __restrict__ sdown,
                               const float* __restrict__ eo, const float* __restrict__ topw,
                               const int* __restrict__ tok_slot, float* __restrict__ xout) {
    int t = blockIdx.x, tid = threadIdx.x;
    int c = tid * 4;
    int s0 = tok_slot[t * 2], s1 = tok_slot[t * 2 + 1];
    float w0 = topw[t * 2], w1 = topw[t * 2 + 1];
    float4 a  = *(const float4*)(x1 + (size_t)t * DD + c);
    float4 sd = *(const float4*)(sdown + (size_t)t * DD + c);
    float4 e0 = *(const float4*)(eo + (size_t)s0 * DD + c);
    float4 e1 = *(const float4*)(eo + (size_t)s1 * DD + c);
    float* o = xout + (size_t)t * DD + c;
    o[0] = a.x + sd.x + w0 * e0.x + w1 * e1.x;
    o[1] = a.y + sd.y + w0 * e0.y + w1 * e1.y;
    o[2] = a.z + sd.z + w0 * e0.z + w1 * e1.z;
    o[3] = a.w + sd.w + w0 * e0.w + w1 * e1.w;
}

// ---------------- launch ------------------------------------------------------
extern "C" void kernel_launch(void* const* d_in, const int* in_sizes, int n_in,
                              void* d_out, int out_size) {
    const float* x      = (const float*)d_in[0];
    const float* ln1_g  = (const float*)d_in[1];
    const float* ln1_b  = (const float*)d_in[2];
    const float* Wqkv   = (const float*)d_in[3];
    const float* bqkv   = (const float*)d_in[4];
    const float* Wo     = (const float*)d_in[5];
    const float* bo     = (const float*)d_in[6];
    const float* ln2_g  = (const float*)d_in[7];
    const float* ln2_b  = (const float*)d_in[8];
    const float* Wg     = (const float*)d_in[9];
    const float* We_up  = (const float*)d_in[10];
    const float* be_up  = (const float*)d_in[11];
    const float* We_dn  = (const float*)d_in[12];
    const float* be_dn  = (const float*)d_in[13];
    const float* Ws_up  = (const float*)d_in[14];
    const float* bs_up  = (const float*)d_in[15];
    const float* Ws_dn  = (const float*)d_in[16];
    const float* bs_dn  = (const float*)d_in[17];

    float* F = nullptr; int* I = nullptr;
    __nv_bfloat16* BH = nullptr; __nv_bfloat16* BL = nullptr;
    cudaGetSymbolAddress((void**)&F, g_f);
    cudaGetSymbolAddress((void**)&I, g_i);
    cudaGetSymbolAddress((void**)&BH, g_bh);
    cudaGetSymbolAddress((void**)&BL, g_bl);

    static bool attr_done = false;
    if (!attr_done) {
        cudaFuncSetAttribute(hgemm_nt<0>, cudaFuncAttributeMaxDynamicSharedMemorySize, SMEM_GEMM);
        cudaFuncSetAttribute(hgemm_nt<1>, cudaFuncAttributeMaxDynamicSharedMemorySize, SMEM_GEMM);
        cudaFuncSetAttribute(hgemm_nt<2>, cudaFuncAttributeMaxDynamicSharedMemorySize, SMEM_GEMM);
        cudaFuncSetAttribute(hgemm_nt<3>, cudaFuncAttributeMaxDynamicSharedMemorySize, SMEM_GEMM);
        cudaFuncSetAttribute(attn_mma_kernel, cudaFuncAttributeMaxDynamicSharedMemorySize, ATTN_SMEM);
        attr_done = true;
    }

    float* x1    = F + OFF_X1;
    float* h2f   = F + OFF_H2F;
    float* sdown = F + OFF_SDOWN;
    float* eob   = F + OFF_EO;
    float* probs = F + OFF_PROBS;
    float* topw  = F + OFF_TOPW;
    int* slot_tok = I + IOFF_SLOT;
    int* tok_slot = I + IOFF_TOKSLOT;
    int* topi     = I + IOFF_TOPI;
    int* cnt      = I + IOFF_CNT;

    float* outp = (float*)d_out;
    float* auxp = nullptr;
    float* xout = outp;
    if (out_size == TT * DD + 1) { auxp = outp; xout = outp + 1; }

    cudaMemsetAsync(cnt, 0, EE * sizeof(int));

    // 0) ALL weight conversions in one fused kernel
    {
        ConvSrcs cs;
        cs.p[0] = Wqkv; cs.p[1] = Wo; cs.p[2] = We_up;
        cs.p[3] = We_dn; cs.p[4] = Ws_up; cs.p[5] = Ws_dn;
        int nblk = (int)((CONV_TOTAL / 4 + 255) / 256);
        conv_all_kernel<<<nblk, 256>>>(cs, BH, BL);
    }

    // 1) LN1 -> bf16 planes
    ln_kernel<0><<<TT, 256>>>(x, ln1_g, ln1_b, nullptr, BH + BO_H, BL + BO_H);
    // 2) QKV projection -> bf16 planes (EPI=3)
    hgemm_nt<3><<<dim3(24, 32, 1), 128, SMEM_GEMM>>>(
        BH + BO_H, BL + BO_H, BH + BO_WQKV, BL + BO_WQKV, bqkv, nullptr,
        nullptr, BH + BO_QKV, BL + BO_QKV, TT, 3 * DD, DD, nullptr, nullptr, 0, 0, 0, 0, 0);
    // 3) tensor-core causal attention -> bf16 planes
    attn_mma_kernel<<<dim3(SS / 64, Bb * HH), 128, ATTN_SMEM>>>(
        BH + BO_QKV, BL + BO_QKV, BH + BO_ATTN, BL + BO_ATTN);
    // 4) output proj + residual -> x1 fp32
    hgemm_nt<2><<<dim3(8, 32, 1), 128, SMEM_GEMM>>>(
        BH + BO_ATTN, BL + BO_ATTN, BH + BO_WO, BL + BO_WO, bo, x,
        x1, nullptr, nullptr, TT, DD, DD, nullptr, nullptr, 0, 0, 0, 0, 0);
    // 5) LN2 -> fp32 + bf16 planes
    ln_kernel<1><<<TT, 256>>>(x1, ln2_g, ln2_b, h2f, BH + BO_H2, BL + BO_H2);
    // 6) router
    router_kernel<<<TT, 128>>>(h2f, Wg, probs, topw, topi, slot_tok, tok_slot, cnt);
    // 7) aux loss
    if (auxp) aux_kernel<<<1, 512>>>(probs, topi, auxp);
    // 8) expert up (gathered, gelu -> bf16 planes)
    hgemm_nt<1><<<dim3(32, 32, 4), 128, SMEM_GEMM>>>(
        BH + BO_H2, BL + BO_H2, BH + BO_WEUP, BL + BO_WEUP, be_up, nullptr,
        nullptr, BH + BO_UPB, BL + BO_UPB, TT, HIDD, DD, slot_tok, cnt,
        0, (size_t)HIDD * DD, (size_t)HIDD, (size_t)TT * HIDD, (size_t)TT);
    // 9) expert down -> eob fp32
    hgemm_nt<0><<<dim3(8, 32, 4), 128, SMEM_GEMM>>>(
        BH + BO_UPB, BL + BO_UPB, BH + BO_WEDN, BL + BO_WEDN, be_dn, nullptr,
        eob, nullptr, nullptr, TT, DD, HIDD, nullptr, cnt,
        (size_t)TT * HIDD, (size_t)DD * HIDD, (size_t)DD, (size_t)TT * DD, 0);
    // 10) shared expert up (gelu -> bf16 planes)
    hgemm_nt<1><<<dim3(32, 32, 1), 128, SMEM_GEMM>>>(
        BH + BO_H2, BL + BO_H2, BH + BO_WSUP, BL + BO_WSUP, bs_up, nullptr,
        nullptr, BH + BO_SUP, BL + BO_SUP, TT, HIDD, DD, nullptr, nullptr, 0, 0, 0, 0, 0);
    // 11) shared expert down -> sdown fp32
    hgemm_nt<0><<<dim3(8, 32, 1), 128, SMEM_GEMM>>>(
        BH + BO_SUP, BL + BO_SUP, BH + BO_WSDN, BL + BO_WSDN, bs_dn, nullptr,
        sdown, nullptr, nullptr, TT, DD, HIDD, nullptr, nullptr, 0, 0, 0, 0, 0);
    // 12) combine
    combine_kernel<<<TT, 256>>>(x1, sdown, eob, topw, tok_slot, xout);
}